// round 1
// baseline (speedup 1.0000x reference)
#include <cuda_runtime.h>
#include <math.h>

// Problem constants (fixed by dataset)
constexpr int N_ROWS  = 400000;
constexpr int TILE    = 64;
constexpr int THREADS = 256;
constexpr int NT      = N_ROWS / TILE;   // 6250
constexpr int KPAD    = 160;             // 153 padded with zero W rows

// Shared-memory float offsets
constexpr int OFF_WSO = 0;                       // [160][128] (rows 153..159 zero)
constexpr int OFF_WG  = OFF_WSO + KPAD * 128;    // [128][64]
constexpr int OFF_WD  = OFF_WG + 128 * 64;       // [64][16]
constexpr int OFF_WU  = OFF_WD + 64 * 16;        // [16][64]
constexpr int OFF_WDS = OFF_WU + 16 * 64;        // [64][4] (col 3 pad)
constexpr int OFF_BSO = OFF_WDS + 64 * 4;        // [128]
constexpr int OFF_BG  = OFF_BSO + 128;           // [64]
constexpr int OFF_BDS = OFF_BG + 64;             // [4]
constexpr int OFF_A   = OFF_BDS + 4;             // [64][160] concat tile
constexpr int OFF_Z   = OFF_A + 64 * 160;        // [64][3][16]
constexpr int OFF_SO  = OFF_Z + 64 * 48;         // [64][128] s_out (pre-silu)
constexpr int OFF_G   = OFF_SO + 64 * 128;       // [64][64] gate (also vs scratch)
constexpr int SMEM_FLOATS = OFF_G + 64 * 64;     // 56772 floats = 227088 B

__device__ __forceinline__ float sigm(float x) { return 1.0f / (1.0f + __expf(-x)); }

__global__ void __launch_bounds__(THREADS, 1)
fused_tpp_kernel(const float* __restrict__ gs, const float* __restrict__ gv,
                 const float* __restrict__ gframes,
                 const float* __restrict__ gWd, const float* __restrict__ gWds,
                 const float* __restrict__ gbds, const float* __restrict__ gWu,
                 const float* __restrict__ gWso, const float* __restrict__ gbso,
                 const float* __restrict__ gWg, const float* __restrict__ gbg,
                 float* __restrict__ out)
{
    extern __shared__ float sm[];
    float* sWso = sm + OFF_WSO;
    float* sWg  = sm + OFF_WG;
    float* sWd  = sm + OFF_WD;
    float* sWu  = sm + OFF_WU;
    float* sWds = sm + OFF_WDS;
    float* sbso = sm + OFF_BSO;
    float* sbg  = sm + OFF_BG;
    float* sbds = sm + OFF_BDS;
    float* sA   = sm + OFF_A;
    float* sZ   = sm + OFF_Z;
    float* sSo  = sm + OFF_SO;
    float* sG   = sm + OFF_G;

    const int tid = threadIdx.x;

    // ---- one-time weight staging ----
    for (int i = tid; i < 153 * 128; i += THREADS) sWso[i] = gWso[i];
    for (int i = 153 * 128 + tid; i < KPAD * 128; i += THREADS) sWso[i] = 0.0f;
    for (int i = tid; i < 128 * 64; i += THREADS) sWg[i] = gWg[i];
    for (int i = tid; i < 64 * 16; i += THREADS) sWd[i] = gWd[i];
    for (int i = tid; i < 16 * 64; i += THREADS) sWu[i] = gWu[i];
    for (int i = tid; i < 64; i += THREADS) {
        sWds[i * 4 + 0] = gWds[i * 3 + 0];
        sWds[i * 4 + 1] = gWds[i * 3 + 1];
        sWds[i * 4 + 2] = gWds[i * 3 + 2];
        sWds[i * 4 + 3] = 0.0f;
    }
    if (tid < 128) sbso[tid] = gbso[tid];
    if (tid < 64)  sbg[tid]  = gbg[tid];
    if (tid < 4)   sbds[tid] = (tid < 3) ? gbds[tid] : 0.0f;
    // zero the permanently-unused concat pad columns 153..159 (once)
    for (int i = tid; i < TILE * 7; i += THREADS) {
        int r = i / 7, c = 153 + (i % 7);
        sA[r * 160 + c] = 0.0f;
    }
    __syncthreads();

    float* outS = out;
    float* outV = out + (size_t)N_ROWS * 128;

    for (int tile = blockIdx.x; tile < NT; tile += gridDim.x) {
        const int row0 = tile * TILE;

        // ---- Phase A1: stage s into concat cols [0,128) ----
        {
            const float4* sg4 = (const float4*)(gs + (size_t)row0 * 128);
            for (int i = tid; i < TILE * 32; i += THREADS) {
                int r = i >> 5, c = i & 31;
                float4 x = sg4[r * 32 + c];
                *(float4*)&sA[r * 160 + c * 4] = x;
            }
        }

        // ---- Phase A2: z = v^T @ W_down (per thread: 1 row, 4 h-cols, all 3 f) ----
        {
            const int r = tid >> 2, j = tid & 3, h0 = j * 4;
            const float4* vr = (const float4*)(gv + (size_t)(row0 + r) * 192);
            float az[12];
            #pragma unroll
            for (int i = 0; i < 12; i++) az[i] = 0.0f;
            #pragma unroll 4
            for (int kc = 0; kc < 16; kc++) {
                float4 p0 = vr[kc * 3 + 0];
                float4 p1 = vr[kc * 3 + 1];
                float4 p2 = vr[kc * 3 + 2];
                float vk[4][3] = {{p0.x, p0.y, p0.z}, {p0.w, p1.x, p1.y},
                                  {p1.z, p1.w, p2.x}, {p2.y, p2.z, p2.w}};
                #pragma unroll
                for (int kk = 0; kk < 4; kk++) {
                    const int k = kc * 4 + kk;
                    float4 w = *(const float4*)&sWd[k * 16 + h0];
                    az[0] += vk[kk][0] * w.x; az[1]  += vk[kk][0] * w.y;
                    az[2] += vk[kk][0] * w.z; az[3]  += vk[kk][0] * w.w;
                    az[4] += vk[kk][1] * w.x; az[5]  += vk[kk][1] * w.y;
                    az[6] += vk[kk][1] * w.z; az[7]  += vk[kk][1] * w.w;
                    az[8] += vk[kk][2] * w.x; az[9]  += vk[kk][2] * w.y;
                    az[10]+= vk[kk][2] * w.z; az[11] += vk[kk][2] * w.w;
                }
            }
            #pragma unroll
            for (int i = 0; i < 4; i++) {
                float z0 = az[i], z1 = az[4 + i], z2 = az[8 + i];
                sZ[r * 48 + 0  + h0 + i] = z0;
                sZ[r * 48 + 16 + h0 + i] = z1;
                sZ[r * 48 + 32 + h0 + i] = z2;
                sA[r * 160 + 137 + h0 + i] = sqrtf(z0 * z0 + z1 * z1 + z2 * z2);
            }
        }

        // ---- Phase A3: vs = silu(v^T @ W_down_s + b) -> scratch (sG region) ----
        if (tid < TILE * 3) {
            const int r = tid / 3, f = tid % 3;
            const float* vr = gv + (size_t)(row0 + r) * 192;
            float a0 = 0.f, a1 = 0.f, a2 = 0.f;
            #pragma unroll 8
            for (int k = 0; k < 64; k++) {
                float vk = vr[k * 3 + f];
                a0 += vk * sWds[k * 4 + 0];
                a1 += vk * sWds[k * 4 + 1];
                a2 += vk * sWds[k * 4 + 2];
            }
            a0 += sbds[0]; a1 += sbds[1]; a2 += sbds[2];
            sG[r * 9 + f * 3 + 0] = a0 * sigm(a0);
            sG[r * 9 + f * 3 + 1] = a1 * sigm(a1);
            sG[r * 9 + f * 3 + 2] = a2 * sigm(a2);
        }
        __syncthreads();

        // ---- Phase A4: scalarized = frames @ vs -> concat cols [128,137) ----
        if (tid < TILE * 3) {
            const int r = tid / 3, f = tid % 3;
            const float* fr = gframes + (size_t)(row0 + r) * 9 + f * 3;
            float f0 = fr[0], f1 = fr[1], f2 = fr[2];
            #pragma unroll
            for (int d = 0; d < 3; d++) {
                float val = f0 * sG[r * 9 + 0 + d] + f1 * sG[r * 9 + 3 + d] +
                            f2 * sG[r * 9 + 6 + d];
                sA[r * 160 + 128 + f * 3 + d] = val;
            }
        }
        __syncthreads();

        // ---- Phase B: s_out = concat @ W_sout + b ; emit silu(s_out), keep s_out ----
        {
            const int rg = tid >> 5, cg = tid & 31;
            const int r0 = rg * 8, c0 = cg * 4;
            float acc[8][4];
            #pragma unroll
            for (int i = 0; i < 8; i++)
                #pragma unroll
                for (int d = 0; d < 4; d++) acc[i][d] = 0.0f;
            #pragma unroll 4
            for (int k = 0; k < KPAD; k++) {
                float4 w = *(const float4*)&sWso[k * 128 + c0];
                #pragma unroll
                for (int i = 0; i < 8; i++) {
                    float a = sA[(r0 + i) * 160 + k];
                    acc[i][0] += a * w.x; acc[i][1] += a * w.y;
                    acc[i][2] += a * w.z; acc[i][3] += a * w.w;
                }
            }
            float4 b4 = *(const float4*)&sbso[c0];
            #pragma unroll
            for (int i = 0; i < 8; i++) {
                const int r = r0 + i;
                float4 so;
                so.x = acc[i][0] + b4.x; so.y = acc[i][1] + b4.y;
                so.z = acc[i][2] + b4.z; so.w = acc[i][3] + b4.w;
                *(float4*)&sSo[r * 128 + c0] = so;
                float4 o;
                o.x = so.x * sigm(so.x); o.y = so.y * sigm(so.y);
                o.z = so.z * sigm(so.z); o.w = so.w * sigm(so.w);
                *(float4*)&outS[(size_t)(row0 + r) * 128 + c0] = o;
            }
        }
        __syncthreads();

        // ---- Phase C: gate = sigmoid(s_out @ W_gate + b) ----
        {
            const int rg = tid >> 5, cg = tid & 31;
            const int r0 = rg * 8, c0 = cg * 2;
            float acc[8][2];
            #pragma unroll
            for (int i = 0; i < 8; i++) { acc[i][0] = 0.0f; acc[i][1] = 0.0f; }
            #pragma unroll 4
            for (int k = 0; k < 128; k++) {
                float2 w = *(const float2*)&sWg[k * 64 + c0];
                #pragma unroll
                for (int i = 0; i < 8; i++) {
                    float a = sSo[(r0 + i) * 128 + k];
                    acc[i][0] += a * w.x; acc[i][1] += a * w.y;
                }
            }
            float b0 = sbg[c0], b1 = sbg[c0 + 1];
            #pragma unroll
            for (int i = 0; i < 8; i++) {
                float2 g;
                g.x = sigm(acc[i][0] + b0);
                g.y = sigm(acc[i][1] + b1);
                *(float2*)&sG[(r0 + i) * 64 + c0] = g;
            }
        }
        __syncthreads();

        // ---- Phase D: v_up = z @ W_up ; v_out[o][f] = v_up[f][o] * gate[o] ----
        {
            const int r = tid >> 2, j = tid & 3, o0 = j * 16;
            float z[3][16];
            #pragma unroll
            for (int f = 0; f < 3; f++)
                #pragma unroll
                for (int q = 0; q < 4; q++) {
                    float4 zz = *(const float4*)&sZ[r * 48 + f * 16 + q * 4];
                    z[f][q * 4 + 0] = zz.x; z[f][q * 4 + 1] = zz.y;
                    z[f][q * 4 + 2] = zz.z; z[f][q * 4 + 3] = zz.w;
                }
            float g[16];
            #pragma unroll
            for (int q = 0; q < 4; q++) {
                float4 gg = *(const float4*)&sG[r * 64 + o0 + q * 4];
                g[q * 4 + 0] = gg.x; g[q * 4 + 1] = gg.y;
                g[q * 4 + 2] = gg.z; g[q * 4 + 3] = gg.w;
            }
            float* ov = outV + (size_t)(row0 + r) * 192 + o0 * 3;
            #pragma unroll
            for (int oq = 0; oq < 4; oq++) {
                float acc[3][4];
                #pragma unroll
                for (int f = 0; f < 3; f++)
                    #pragma unroll
                    for (int m = 0; m < 4; m++) acc[f][m] = 0.0f;
                #pragma unroll
                for (int h = 0; h < 16; h++) {
                    float4 w = *(const float4*)&sWu[h * 64 + o0 + oq * 4];
                    acc[0][0] += z[0][h] * w.x; acc[0][1] += z[0][h] * w.y;
                    acc[0][2] += z[0][h] * w.z; acc[0][3] += z[0][h] * w.w;
                    acc[1][0] += z[1][h] * w.x; acc[1][1] += z[1][h] * w.y;
                    acc[1][2] += z[1][h] * w.z; acc[1][3] += z[1][h] * w.w;
                    acc[2][0] += z[2][h] * w.x; acc[2][1] += z[2][h] * w.y;
                    acc[2][2] += z[2][h] * w.z; acc[2][3] += z[2][h] * w.w;
                }
                float vals[12];
                #pragma unroll
                for (int m = 0; m < 4; m++) {
                    float gm = g[oq * 4 + m];
                    vals[m * 3 + 0] = acc[0][m] * gm;
                    vals[m * 3 + 1] = acc[1][m] * gm;
                    vals[m * 3 + 2] = acc[2][m] * gm;
                }
                float4 t0 = {vals[0], vals[1], vals[2],  vals[3]};
                float4 t1 = {vals[4], vals[5], vals[6],  vals[7]};
                float4 t2 = {vals[8], vals[9], vals[10], vals[11]};
                *(float4*)(ov + oq * 12 + 0) = t0;
                *(float4*)(ov + oq * 12 + 4) = t1;
                *(float4*)(ov + oq * 12 + 8) = t2;
            }
        }
        __syncthreads();   // protect sZ/sG/sA before next tile's phase A
    }
}

extern "C" void kernel_launch(void* const* d_in, const int* in_sizes, int n_in,
                              void* d_out, int out_size) {
    const float* s      = (const float*)d_in[0];
    const float* v      = (const float*)d_in[1];
    const float* frames = (const float*)d_in[2];
    const float* Wd     = (const float*)d_in[3];
    const float* Wds    = (const float*)d_in[4];
    const float* bds    = (const float*)d_in[5];
    const float* Wu     = (const float*)d_in[6];
    const float* Wso    = (const float*)d_in[7];
    const float* bso    = (const float*)d_in[8];
    const float* Wg     = (const float*)d_in[9];
    const float* bg     = (const float*)d_in[10];
    float* out          = (float*)d_out;

    int dev = 0;
    cudaGetDevice(&dev);
    int smCount = 148;
    cudaDeviceGetAttribute(&smCount, cudaDevAttrMultiProcessorCount, dev);

    const size_t smem = (size_t)SMEM_FLOATS * sizeof(float);
    cudaFuncSetAttribute(fused_tpp_kernel,
                         cudaFuncAttributeMaxDynamicSharedMemorySize, (int)smem);
    fused_tpp_kernel<<<smCount, THREADS, smem>>>(s, v, frames, Wd, Wds, bds, Wu,
                                                 Wso, bso, Wg, bg, out);
}

// round 2
// speedup vs baseline: 1.0082x; 1.0082x over previous
#include <cuda_runtime.h>
#include <math.h>

typedef unsigned long long ull;

// Problem constants (fixed by dataset)
constexpr int N_ROWS  = 400000;
constexpr int TILE    = 64;
constexpr int THREADS = 256;
constexpr int NT      = N_ROWS / TILE;   // 6250
constexpr int KPAD    = 160;             // 153 padded with zero W rows
constexpr int WSO_STR = 164;             // transposed W_sout row stride (floats)
constexpr int WG_STR  = 132;             // transposed W_gate row stride (floats)

// Shared-memory float offsets
constexpr int OFF_WSO = 0;                         // [128][164] transposed, k-major
constexpr int OFF_WG  = OFF_WSO + 128 * WSO_STR;   // [64][132] transposed, k-major
constexpr int OFF_WD  = OFF_WG + 64 * WG_STR;      // [64][16]
constexpr int OFF_WU  = OFF_WD + 64 * 16;          // [16][64]
constexpr int OFF_WDS = OFF_WU + 16 * 64;          // [64][4] (col 3 pad)
constexpr int OFF_BSO = OFF_WDS + 64 * 4;          // [128]
constexpr int OFF_BG  = OFF_BSO + 128;             // [64]
constexpr int OFF_BDS = OFF_BG + 64;               // [4]
constexpr int OFF_A   = OFF_BDS + 4;               // [64][160] concat tile
constexpr int OFF_Z   = OFF_A + 64 * 160;          // [64][3][16]
constexpr int OFF_SO  = OFF_Z + 64 * 48;           // [64][128] s_out (pre-silu)
constexpr int OFF_G   = OFF_SO + 64 * 128;         // [64][64] gate (also vs scratch)
constexpr int SMEM_FLOATS = OFF_G + 64 * 64;       // 57540 floats = 230160 B

__device__ __forceinline__ float sigm(float x) { return 1.0f / (1.0f + __expf(-x)); }

__device__ __forceinline__ void fma2(ull& d, ull a, ull b) {
    asm("fma.rn.f32x2 %0, %1, %2, %0;" : "+l"(d) : "l"(a), "l"(b));
}
__device__ __forceinline__ float2 unpack2(ull x) {
    float2 r;
    asm("mov.b64 {%0, %1}, %2;" : "=f"(r.x), "=f"(r.y) : "l"(x));
    return r;
}

__global__ void __launch_bounds__(THREADS, 1)
fused_tpp_kernel(const float* __restrict__ gs, const float* __restrict__ gv,
                 const float* __restrict__ gframes,
                 const float* __restrict__ gWd, const float* __restrict__ gWds,
                 const float* __restrict__ gbds, const float* __restrict__ gWu,
                 const float* __restrict__ gWso, const float* __restrict__ gbso,
                 const float* __restrict__ gWg, const float* __restrict__ gbg,
                 float* __restrict__ out)
{
    extern __shared__ float sm[];
    float* sWsoT = sm + OFF_WSO;
    float* sWgT  = sm + OFF_WG;
    float* sWd   = sm + OFF_WD;
    float* sWu   = sm + OFF_WU;
    float* sWds  = sm + OFF_WDS;
    float* sbso  = sm + OFF_BSO;
    float* sbg   = sm + OFF_BG;
    float* sbds  = sm + OFF_BDS;
    float* sA    = sm + OFF_A;
    float* sZ    = sm + OFF_Z;
    float* sSo   = sm + OFF_SO;
    float* sG    = sm + OFF_G;

    const int tid = threadIdx.x;

    // ---- one-time weight staging (transposed for the two big GEMMs) ----
    for (int i = tid; i < 128 * KPAD; i += THREADS) {
        int c = i / KPAD, k = i % KPAD;
        sWsoT[c * WSO_STR + k] = (k < 153) ? gWso[k * 128 + c] : 0.0f;
    }
    for (int i = tid; i < 64 * 128; i += THREADS) {
        int c = i / 128, k = i % 128;
        sWgT[c * WG_STR + k] = gWg[k * 64 + c];
    }
    for (int i = tid; i < 64 * 16; i += THREADS) sWd[i] = gWd[i];
    for (int i = tid; i < 16 * 64; i += THREADS) sWu[i] = gWu[i];
    for (int i = tid; i < 64; i += THREADS) {
        sWds[i * 4 + 0] = gWds[i * 3 + 0];
        sWds[i * 4 + 1] = gWds[i * 3 + 1];
        sWds[i * 4 + 2] = gWds[i * 3 + 2];
        sWds[i * 4 + 3] = 0.0f;
    }
    if (tid < 128) sbso[tid] = gbso[tid];
    if (tid < 64)  sbg[tid]  = gbg[tid];
    if (tid < 4)   sbds[tid] = (tid < 3) ? gbds[tid] : 0.0f;
    // zero the permanently-unused concat pad columns 153..159 (once)
    for (int i = tid; i < TILE * 7; i += THREADS) {
        int r = i / 7, c = 153 + (i % 7);
        sA[r * 160 + c] = 0.0f;
    }
    __syncthreads();

    float* outS = out;
    float* outV = out + (size_t)N_ROWS * 128;

    for (int tile = blockIdx.x; tile < NT; tile += gridDim.x) {
        const int row0 = tile * TILE;

        // ---- Phase A1: stage s into concat cols [0,128) ----
        {
            const float4* sg4 = (const float4*)(gs + (size_t)row0 * 128);
            for (int i = tid; i < TILE * 32; i += THREADS) {
                int r = i >> 5, c = i & 31;
                float4 x = sg4[r * 32 + c];
                *(float4*)&sA[r * 160 + c * 4] = x;
            }
        }

        // ---- Phase A2: z = v^T @ W_down (per thread: 1 row, 4 h-cols, all 3 f) ----
        {
            const int r = tid >> 2, j = tid & 3, h0 = j * 4;
            const float4* vr = (const float4*)(gv + (size_t)(row0 + r) * 192);
            float az[12];
            #pragma unroll
            for (int i = 0; i < 12; i++) az[i] = 0.0f;
            #pragma unroll 4
            for (int kc = 0; kc < 16; kc++) {
                float4 p0 = vr[kc * 3 + 0];
                float4 p1 = vr[kc * 3 + 1];
                float4 p2 = vr[kc * 3 + 2];
                float vk[4][3] = {{p0.x, p0.y, p0.z}, {p0.w, p1.x, p1.y},
                                  {p1.z, p1.w, p2.x}, {p2.y, p2.z, p2.w}};
                #pragma unroll
                for (int kk = 0; kk < 4; kk++) {
                    const int k = kc * 4 + kk;
                    float4 w = *(const float4*)&sWd[k * 16 + h0];
                    az[0] += vk[kk][0] * w.x; az[1]  += vk[kk][0] * w.y;
                    az[2] += vk[kk][0] * w.z; az[3]  += vk[kk][0] * w.w;
                    az[4] += vk[kk][1] * w.x; az[5]  += vk[kk][1] * w.y;
                    az[6] += vk[kk][1] * w.z; az[7]  += vk[kk][1] * w.w;
                    az[8] += vk[kk][2] * w.x; az[9]  += vk[kk][2] * w.y;
                    az[10]+= vk[kk][2] * w.z; az[11] += vk[kk][2] * w.w;
                }
            }
            #pragma unroll
            for (int i = 0; i < 4; i++) {
                float z0 = az[i], z1 = az[4 + i], z2 = az[8 + i];
                sZ[r * 48 + 0  + h0 + i] = z0;
                sZ[r * 48 + 16 + h0 + i] = z1;
                sZ[r * 48 + 32 + h0 + i] = z2;
                sA[r * 160 + 137 + h0 + i] = sqrtf(z0 * z0 + z1 * z1 + z2 * z2);
            }
        }

        // ---- Phase A3: vs = silu(v^T @ W_down_s + b) -> scratch (sG region) ----
        if (tid < TILE * 3) {
            const int r = tid / 3, f = tid % 3;
            const float* vr = gv + (size_t)(row0 + r) * 192;
            float a0 = 0.f, a1 = 0.f, a2 = 0.f;
            #pragma unroll 8
            for (int k = 0; k < 64; k++) {
                float vk = vr[k * 3 + f];
                a0 += vk * sWds[k * 4 + 0];
                a1 += vk * sWds[k * 4 + 1];
                a2 += vk * sWds[k * 4 + 2];
            }
            a0 += sbds[0]; a1 += sbds[1]; a2 += sbds[2];
            sG[r * 9 + f * 3 + 0] = a0 * sigm(a0);
            sG[r * 9 + f * 3 + 1] = a1 * sigm(a1);
            sG[r * 9 + f * 3 + 2] = a2 * sigm(a2);
        }
        __syncthreads();

        // ---- Phase A4: scalarized = frames @ vs -> concat cols [128,137) ----
        if (tid < TILE * 3) {
            const int r = tid / 3, f = tid % 3;
            const float* fr = gframes + (size_t)(row0 + r) * 9 + f * 3;
            float f0 = fr[0], f1 = fr[1], f2 = fr[2];
            #pragma unroll
            for (int d = 0; d < 3; d++) {
                float val = f0 * sG[r * 9 + 0 + d] + f1 * sG[r * 9 + 3 + d] +
                            f2 * sG[r * 9 + 6 + d];
                sA[r * 160 + 128 + f * 3 + d] = val;
            }
        }
        __syncthreads();

        // ---- Phase B: s_out = concat @ W_sout + b (f32x2, k-pair packed) ----
        // lane cg handles cols {cg, cg+32, cg+64, cg+96}; warp rg rows rg*8..rg*8+7
        {
            const int rg = tid >> 5, cg = tid & 31;
            const int r0 = rg * 8;
            ull acc[8][4];
            #pragma unroll
            for (int i = 0; i < 8; i++)
                #pragma unroll
                for (int j = 0; j < 4; j++) acc[i][j] = 0ULL;
            #pragma unroll 2
            for (int k = 0; k < KPAD; k += 4) {
                ulonglong2 w[4];
                #pragma unroll
                for (int j = 0; j < 4; j++)
                    w[j] = *(const ulonglong2*)&sWsoT[(cg + 32 * j) * WSO_STR + k];
                #pragma unroll
                for (int i = 0; i < 8; i++) {
                    ulonglong2 a2 = *(const ulonglong2*)&sA[(r0 + i) * 160 + k];
                    #pragma unroll
                    for (int j = 0; j < 4; j++) {
                        fma2(acc[i][j], a2.x, w[j].x);
                        fma2(acc[i][j], a2.y, w[j].y);
                    }
                }
            }
            #pragma unroll
            for (int i = 0; i < 8; i++) {
                #pragma unroll
                for (int j = 0; j < 4; j++) {
                    const int c = cg + 32 * j;
                    float2 p = unpack2(acc[i][j]);
                    sSo[(r0 + i) * 128 + c] = p.x + p.y + sbso[c];
                }
            }
        }
        __syncthreads();

        // ---- Phase B2: silu(s_out) -> global (vectorized) ----
        {
            #pragma unroll
            for (int q = 0; q < 8; q++) {
                const int idx = tid + q * THREADS;      // 2048 quads
                const int r = idx >> 5, c4 = (idx & 31) * 4;
                float4 so = *(const float4*)&sSo[r * 128 + c4];
                float4 o;
                o.x = so.x * sigm(so.x); o.y = so.y * sigm(so.y);
                o.z = so.z * sigm(so.z); o.w = so.w * sigm(so.w);
                *(float4*)&outS[(size_t)(row0 + r) * 128 + c4] = o;
            }
        }

        // ---- Phase C: gate = sigmoid(s_out @ W_gate + b) (f32x2, k-pair packed) ----
        // lane cg handles cols {cg, cg+32}; warp rg rows rg*8..rg*8+7
        {
            const int rg = tid >> 5, cg = tid & 31;
            const int r0 = rg * 8;
            ull acc[8][2];
            #pragma unroll
            for (int i = 0; i < 8; i++) { acc[i][0] = 0ULL; acc[i][1] = 0ULL; }
            #pragma unroll 2
            for (int k = 0; k < 128; k += 4) {
                ulonglong2 w0 = *(const ulonglong2*)&sWgT[cg * WG_STR + k];
                ulonglong2 w1 = *(const ulonglong2*)&sWgT[(cg + 32) * WG_STR + k];
                #pragma unroll
                for (int i = 0; i < 8; i++) {
                    ulonglong2 a2 = *(const ulonglong2*)&sSo[(r0 + i) * 128 + k];
                    fma2(acc[i][0], a2.x, w0.x);
                    fma2(acc[i][0], a2.y, w0.y);
                    fma2(acc[i][1], a2.x, w1.x);
                    fma2(acc[i][1], a2.y, w1.y);
                }
            }
            #pragma unroll
            for (int i = 0; i < 8; i++) {
                #pragma unroll
                for (int j = 0; j < 2; j++) {
                    const int c = cg + 32 * j;
                    float2 p = unpack2(acc[i][j]);
                    sG[(r0 + i) * 64 + c] = sigm(p.x + p.y + sbg[c]);
                }
            }
        }
        __syncthreads();

        // ---- Phase D: v_up = z @ W_up ; v_out[o][f] = v_up[f][o] * gate[o] ----
        {
            const int r = tid >> 2, j = tid & 3, o0 = j * 16;
            float z[3][16];
            #pragma unroll
            for (int f = 0; f < 3; f++)
                #pragma unroll
                for (int q = 0; q < 4; q++) {
                    float4 zz = *(const float4*)&sZ[r * 48 + f * 16 + q * 4];
                    z[f][q * 4 + 0] = zz.x; z[f][q * 4 + 1] = zz.y;
                    z[f][q * 4 + 2] = zz.z; z[f][q * 4 + 3] = zz.w;
                }
            float g[16];
            #pragma unroll
            for (int q = 0; q < 4; q++) {
                float4 gg = *(const float4*)&sG[r * 64 + o0 + q * 4];
                g[q * 4 + 0] = gg.x; g[q * 4 + 1] = gg.y;
                g[q * 4 + 2] = gg.z; g[q * 4 + 3] = gg.w;
            }
            float* ov = outV + (size_t)(row0 + r) * 192 + o0 * 3;
            #pragma unroll
            for (int oq = 0; oq < 4; oq++) {
                float acc[3][4];
                #pragma unroll
                for (int f = 0; f < 3; f++)
                    #pragma unroll
                    for (int m = 0; m < 4; m++) acc[f][m] = 0.0f;
                #pragma unroll
                for (int h = 0; h < 16; h++) {
                    float4 w = *(const float4*)&sWu[h * 64 + o0 + oq * 4];
                    acc[0][0] += z[0][h] * w.x; acc[0][1] += z[0][h] * w.y;
                    acc[0][2] += z[0][h] * w.z; acc[0][3] += z[0][h] * w.w;
                    acc[1][0] += z[1][h] * w.x; acc[1][1] += z[1][h] * w.y;
                    acc[1][2] += z[1][h] * w.z; acc[1][3] += z[1][h] * w.w;
                    acc[2][0] += z[2][h] * w.x; acc[2][1] += z[2][h] * w.y;
                    acc[2][2] += z[2][h] * w.z; acc[2][3] += z[2][h] * w.w;
                }
                float vals[12];
                #pragma unroll
                for (int m = 0; m < 4; m++) {
                    float gm = g[oq * 4 + m];
                    vals[m * 3 + 0] = acc[0][m] * gm;
                    vals[m * 3 + 1] = acc[1][m] * gm;
                    vals[m * 3 + 2] = acc[2][m] * gm;
                }
                float4 t0 = {vals[0], vals[1], vals[2],  vals[3]};
                float4 t1 = {vals[4], vals[5], vals[6],  vals[7]};
                float4 t2 = {vals[8], vals[9], vals[10], vals[11]};
                *(float4*)(ov + oq * 12 + 0) = t0;
                *(float4*)(ov + oq * 12 + 4) = t1;
                *(float4*)(ov + oq * 12 + 8) = t2;
            }
        }
        __syncthreads();   // protect sZ/sG/sA/sSo before next tile's phase A
    }
}

extern "C" void kernel_launch(void* const* d_in, const int* in_sizes, int n_in,
                              void* d_out, int out_size) {
    const float* s      = (const float*)d_in[0];
    const float* v      = (const float*)d_in[1];
    const float* frames = (const float*)d_in[2];
    const float* Wd     = (const float*)d_in[3];
    const float* Wds    = (const float*)d_in[4];
    const float* bds    = (const float*)d_in[5];
    const float* Wu     = (const float*)d_in[6];
    const float* Wso    = (const float*)d_in[7];
    const float* bso    = (const float*)d_in[8];
    const float* Wg     = (const float*)d_in[9];
    const float* bg     = (const float*)d_in[10];
    float* out          = (float*)d_out;

    int dev = 0;
    cudaGetDevice(&dev);
    int smCount = 148;
    cudaDeviceGetAttribute(&smCount, cudaDevAttrMultiProcessorCount, dev);

    const size_t smem = (size_t)SMEM_FLOATS * sizeof(float);
    cudaFuncSetAttribute(fused_tpp_kernel,
                         cudaFuncAttributeMaxDynamicSharedMemorySize, (int)smem);
    fused_tpp_kernel<<<smCount, THREADS, smem>>>(s, v, frames, Wd, Wds, bds, Wu,
                                                 Wso, bso, Wg, bg, out);
}

// round 3
// speedup vs baseline: 1.0688x; 1.0602x over previous
#include <cuda_runtime.h>
#include <math.h>

typedef unsigned long long ull;

// Problem constants (fixed by dataset)
constexpr int N_ROWS  = 400000;
constexpr int TILE    = 64;
constexpr int THREADS = 512;
constexpr int NT      = N_ROWS / TILE;   // 6250
constexpr int KPAD    = 160;             // 153 padded with zero W rows
constexpr int WSO_STR = 164;             // transposed W_sout row stride (floats)
constexpr int WG_STR  = 132;             // transposed W_gate row stride (floats)

// Shared-memory float offsets
constexpr int OFF_WSO = 0;                         // [128][164] transposed, k-major
constexpr int OFF_WG  = OFF_WSO + 128 * WSO_STR;   // [64][132] transposed, k-major
constexpr int OFF_WD  = OFF_WG + 64 * WG_STR;      // [64][16]
constexpr int OFF_WU  = OFF_WD + 64 * 16;          // [16][64]
constexpr int OFF_WDS = OFF_WU + 16 * 64;          // [64][4] (col 3 pad)
constexpr int OFF_BSO = OFF_WDS + 64 * 4;          // [128]
constexpr int OFF_BG  = OFF_BSO + 128;             // [64]
constexpr int OFF_BDS = OFF_BG + 64;               // [4]
constexpr int OFF_A   = OFF_BDS + 4;               // [64][160] concat tile
constexpr int OFF_Z   = OFF_A + 64 * 160;          // [64][3][16]
constexpr int OFF_SO  = OFF_Z + 64 * 48;           // [64][128] s_out (pre-silu)
constexpr int OFF_G   = OFF_SO + 64 * 128;         // [64][64] gate (also vs scratch)
constexpr int SMEM_FLOATS = OFF_G + 64 * 64;       // 57540 floats = 230160 B

__device__ __forceinline__ float sigm(float x) { return 1.0f / (1.0f + __expf(-x)); }

__device__ __forceinline__ void fma2(ull& d, ull a, ull b) {
    asm("fma.rn.f32x2 %0, %1, %2, %0;" : "+l"(d) : "l"(a), "l"(b));
}
__device__ __forceinline__ float2 unpack2(ull x) {
    float2 r;
    asm("mov.b64 {%0, %1}, %2;" : "=f"(r.x), "=f"(r.y) : "l"(x));
    return r;
}

__global__ void __launch_bounds__(THREADS, 1)
fused_tpp_kernel(const float* __restrict__ gs, const float* __restrict__ gv,
                 const float* __restrict__ gframes,
                 const float* __restrict__ gWd, const float* __restrict__ gWds,
                 const float* __restrict__ gbds, const float* __restrict__ gWu,
                 const float* __restrict__ gWso, const float* __restrict__ gbso,
                 const float* __restrict__ gWg, const float* __restrict__ gbg,
                 float* __restrict__ out)
{
    extern __shared__ float sm[];
    float* sWsoT = sm + OFF_WSO;
    float* sWgT  = sm + OFF_WG;
    float* sWd   = sm + OFF_WD;
    float* sWu   = sm + OFF_WU;
    float* sWds  = sm + OFF_WDS;
    float* sbso  = sm + OFF_BSO;
    float* sbg   = sm + OFF_BG;
    float* sbds  = sm + OFF_BDS;
    float* sA    = sm + OFF_A;
    float* sZ    = sm + OFF_Z;
    float* sSo   = sm + OFF_SO;
    float* sG    = sm + OFF_G;

    const int tid = threadIdx.x;

    // ---- one-time weight staging (transposed for the two big GEMMs) ----
    for (int i = tid; i < 128 * KPAD; i += THREADS) {
        int c = i / KPAD, k = i % KPAD;
        sWsoT[c * WSO_STR + k] = (k < 153) ? gWso[k * 128 + c] : 0.0f;
    }
    for (int i = tid; i < 64 * 128; i += THREADS) {
        int c = i / 128, k = i % 128;
        sWgT[c * WG_STR + k] = gWg[k * 64 + c];
    }
    for (int i = tid; i < 64 * 16; i += THREADS) sWd[i] = gWd[i];
    for (int i = tid; i < 16 * 64; i += THREADS) sWu[i] = gWu[i];
    for (int i = tid; i < 64; i += THREADS) {
        sWds[i * 4 + 0] = gWds[i * 3 + 0];
        sWds[i * 4 + 1] = gWds[i * 3 + 1];
        sWds[i * 4 + 2] = gWds[i * 3 + 2];
        sWds[i * 4 + 3] = 0.0f;
    }
    if (tid < 128) sbso[tid] = gbso[tid];
    if (tid < 64)  sbg[tid]  = gbg[tid];
    if (tid < 4)   sbds[tid] = (tid < 3) ? gbds[tid] : 0.0f;
    // zero the permanently-unused concat pad columns 153..159 (once)
    for (int i = tid; i < TILE * 7; i += THREADS) {
        int r = i / 7, c = 153 + (i % 7);
        sA[r * 160 + c] = 0.0f;
    }
    __syncthreads();

    float* outS = out;
    float* outV = out + (size_t)N_ROWS * 128;

    for (int tile = blockIdx.x; tile < NT; tile += gridDim.x) {
        const int row0 = tile * TILE;

        // ---- Phase A1: stage s into concat cols [0,128) ----
        {
            const float4* sg4 = (const float4*)(gs + (size_t)row0 * 128);
            #pragma unroll
            for (int q = 0; q < 4; q++) {
                int i = tid + q * THREADS;               // 2048 float4s
                int r = i >> 5, c = i & 31;
                float4 x = sg4[r * 32 + c];
                *(float4*)&sA[r * 160 + c * 4] = x;
            }
        }

        // ---- Phase A2: z = v^T @ W_down (threads 0..255: 1 row, 4 h-cols, 3 f) ----
        if (tid < 256) {
            const int r = tid >> 2, j = tid & 3, h0 = j * 4;
            const float4* vr = (const float4*)(gv + (size_t)(row0 + r) * 192);
            float az[12];
            #pragma unroll
            for (int i = 0; i < 12; i++) az[i] = 0.0f;
            #pragma unroll 4
            for (int kc = 0; kc < 16; kc++) {
                float4 p0 = vr[kc * 3 + 0];
                float4 p1 = vr[kc * 3 + 1];
                float4 p2 = vr[kc * 3 + 2];
                float vk[4][3] = {{p0.x, p0.y, p0.z}, {p0.w, p1.x, p1.y},
                                  {p1.z, p1.w, p2.x}, {p2.y, p2.z, p2.w}};
                #pragma unroll
                for (int kk = 0; kk < 4; kk++) {
                    const int k = kc * 4 + kk;
                    float4 w = *(const float4*)&sWd[k * 16 + h0];
                    az[0] += vk[kk][0] * w.x; az[1]  += vk[kk][0] * w.y;
                    az[2] += vk[kk][0] * w.z; az[3]  += vk[kk][0] * w.w;
                    az[4] += vk[kk][1] * w.x; az[5]  += vk[kk][1] * w.y;
                    az[6] += vk[kk][1] * w.z; az[7]  += vk[kk][1] * w.w;
                    az[8] += vk[kk][2] * w.x; az[9]  += vk[kk][2] * w.y;
                    az[10]+= vk[kk][2] * w.z; az[11] += vk[kk][2] * w.w;
                }
            }
            #pragma unroll
            for (int i = 0; i < 4; i++) {
                float z0 = az[i], z1 = az[4 + i], z2 = az[8 + i];
                sZ[r * 48 + 0  + h0 + i] = z0;
                sZ[r * 48 + 16 + h0 + i] = z1;
                sZ[r * 48 + 32 + h0 + i] = z2;
                sA[r * 160 + 137 + h0 + i] = sqrtf(z0 * z0 + z1 * z1 + z2 * z2);
            }
        }

        // ---- Phase A3: vs = silu(v^T @ W_down_s + b) -> scratch (sG region) ----
        if (tid >= 256 && tid < 256 + TILE * 3) {
            const int t = tid - 256;
            const int r = t / 3, f = t % 3;
            const float* vr = gv + (size_t)(row0 + r) * 192;
            float a0 = 0.f, a1 = 0.f, a2 = 0.f;
            #pragma unroll 8
            for (int k = 0; k < 64; k++) {
                float vk = vr[k * 3 + f];
                a0 += vk * sWds[k * 4 + 0];
                a1 += vk * sWds[k * 4 + 1];
                a2 += vk * sWds[k * 4 + 2];
            }
            a0 += sbds[0]; a1 += sbds[1]; a2 += sbds[2];
            sG[r * 9 + f * 3 + 0] = a0 * sigm(a0);
            sG[r * 9 + f * 3 + 1] = a1 * sigm(a1);
            sG[r * 9 + f * 3 + 2] = a2 * sigm(a2);
        }
        __syncthreads();

        // ---- Phase A4: scalarized = frames @ vs -> concat cols [128,137) ----
        if (tid < TILE * 3) {
            const int r = tid / 3, f = tid % 3;
            const float* fr = gframes + (size_t)(row0 + r) * 9 + f * 3;
            float f0 = fr[0], f1 = fr[1], f2 = fr[2];
            #pragma unroll
            for (int d = 0; d < 3; d++) {
                float val = f0 * sG[r * 9 + 0 + d] + f1 * sG[r * 9 + 3 + d] +
                            f2 * sG[r * 9 + 6 + d];
                sA[r * 160 + 128 + f * 3 + d] = val;
            }
        }
        __syncthreads();

        // ---- Phase B: s_out = concat @ W_sout + b (f32x2, k-pair packed) ----
        // 16 warps x 4 rows; lane cg covers cols {cg, cg+32, cg+64, cg+96}
        {
            const int rg = tid >> 5, cg = tid & 31;
            const int r0 = rg * 4;
            ull acc[4][4];
            #pragma unroll
            for (int i = 0; i < 4; i++)
                #pragma unroll
                for (int j = 0; j < 4; j++) acc[i][j] = 0ULL;
            #pragma unroll 2
            for (int k = 0; k < KPAD; k += 4) {
                ulonglong2 w[4];
                #pragma unroll
                for (int j = 0; j < 4; j++)
                    w[j] = *(const ulonglong2*)&sWsoT[(cg + 32 * j) * WSO_STR + k];
                #pragma unroll
                for (int i = 0; i < 4; i++) {
                    ulonglong2 a2 = *(const ulonglong2*)&sA[(r0 + i) * 160 + k];
                    #pragma unroll
                    for (int j = 0; j < 4; j++) {
                        fma2(acc[i][j], a2.x, w[j].x);
                        fma2(acc[i][j], a2.y, w[j].y);
                    }
                }
            }
            #pragma unroll
            for (int i = 0; i < 4; i++) {
                #pragma unroll
                for (int j = 0; j < 4; j++) {
                    const int c = cg + 32 * j;
                    float2 p = unpack2(acc[i][j]);
                    sSo[(r0 + i) * 128 + c] = p.x + p.y + sbso[c];
                }
            }
        }
        __syncthreads();

        // ---- Phase B2: silu(s_out) -> global (vectorized) ----
        {
            #pragma unroll
            for (int q = 0; q < 4; q++) {
                const int idx = tid + q * THREADS;      // 2048 quads
                const int r = idx >> 5, c4 = (idx & 31) * 4;
                float4 so = *(const float4*)&sSo[r * 128 + c4];
                float4 o;
                o.x = so.x * sigm(so.x); o.y = so.y * sigm(so.y);
                o.z = so.z * sigm(so.z); o.w = so.w * sigm(so.w);
                *(float4*)&outS[(size_t)(row0 + r) * 128 + c4] = o;
            }
        }

        // ---- Phase C: gate = sigmoid(s_out @ W_gate + b) (f32x2) ----
        // 16 warps x 4 rows; lane cg covers cols {cg, cg+32}
        {
            const int rg = tid >> 5, cg = tid & 31;
            const int r0 = rg * 4;
            ull acc[4][2];
            #pragma unroll
            for (int i = 0; i < 4; i++) { acc[i][0] = 0ULL; acc[i][1] = 0ULL; }
            #pragma unroll 2
            for (int k = 0; k < 128; k += 4) {
                ulonglong2 w0 = *(const ulonglong2*)&sWgT[cg * WG_STR + k];
                ulonglong2 w1 = *(const ulonglong2*)&sWgT[(cg + 32) * WG_STR + k];
                #pragma unroll
                for (int i = 0; i < 4; i++) {
                    ulonglong2 a2 = *(const ulonglong2*)&sSo[(r0 + i) * 128 + k];
                    fma2(acc[i][0], a2.x, w0.x);
                    fma2(acc[i][0], a2.y, w0.y);
                    fma2(acc[i][1], a2.x, w1.x);
                    fma2(acc[i][1], a2.y, w1.y);
                }
            }
            #pragma unroll
            for (int i = 0; i < 4; i++) {
                #pragma unroll
                for (int j = 0; j < 2; j++) {
                    const int c = cg + 32 * j;
                    float2 p = unpack2(acc[i][j]);
                    sG[(r0 + i) * 64 + c] = sigm(p.x + p.y + sbg[c]);
                }
            }
        }
        __syncthreads();

        // ---- Phase D: v_up = z @ W_up ; v_out[o][f] = v_up[f][o] * gate[o] ----
        // 512 threads: 1 row each (tid>>3), 8 out cols (tid&7)*8
        {
            const int r = tid >> 3, j = tid & 7, o0 = j * 8;
            float z[3][16];
            #pragma unroll
            for (int f = 0; f < 3; f++)
                #pragma unroll
                for (int q = 0; q < 4; q++) {
                    float4 zz = *(const float4*)&sZ[r * 48 + f * 16 + q * 4];
                    z[f][q * 4 + 0] = zz.x; z[f][q * 4 + 1] = zz.y;
                    z[f][q * 4 + 2] = zz.z; z[f][q * 4 + 3] = zz.w;
                }
            float g[8];
            #pragma unroll
            for (int q = 0; q < 2; q++) {
                float4 gg = *(const float4*)&sG[r * 64 + o0 + q * 4];
                g[q * 4 + 0] = gg.x; g[q * 4 + 1] = gg.y;
                g[q * 4 + 2] = gg.z; g[q * 4 + 3] = gg.w;
            }
            float* ov = outV + (size_t)(row0 + r) * 192 + o0 * 3;
            #pragma unroll
            for (int oq = 0; oq < 2; oq++) {
                float acc[3][4];
                #pragma unroll
                for (int f = 0; f < 3; f++)
                    #pragma unroll
                    for (int m = 0; m < 4; m++) acc[f][m] = 0.0f;
                #pragma unroll
                for (int h = 0; h < 16; h++) {
                    float4 w = *(const float4*)&sWu[h * 64 + o0 + oq * 4];
                    acc[0][0] += z[0][h] * w.x; acc[0][1] += z[0][h] * w.y;
                    acc[0][2] += z[0][h] * w.z; acc[0][3] += z[0][h] * w.w;
                    acc[1][0] += z[1][h] * w.x; acc[1][1] += z[1][h] * w.y;
                    acc[1][2] += z[1][h] * w.z; acc[1][3] += z[1][h] * w.w;
                    acc[2][0] += z[2][h] * w.x; acc[2][1] += z[2][h] * w.y;
                    acc[2][2] += z[2][h] * w.z; acc[2][3] += z[2][h] * w.w;
                }
                float vals[12];
                #pragma unroll
                for (int m = 0; m < 4; m++) {
                    float gm = g[oq * 4 + m];
                    vals[m * 3 + 0] = acc[0][m] * gm;
                    vals[m * 3 + 1] = acc[1][m] * gm;
                    vals[m * 3 + 2] = acc[2][m] * gm;
                }
                float4 t0 = {vals[0], vals[1], vals[2],  vals[3]};
                float4 t1 = {vals[4], vals[5], vals[6],  vals[7]};
                float4 t2 = {vals[8], vals[9], vals[10], vals[11]};
                *(float4*)(ov + oq * 12 + 0) = t0;
                *(float4*)(ov + oq * 12 + 4) = t1;
                *(float4*)(ov + oq * 12 + 8) = t2;
            }
        }
        __syncthreads();   // protect sZ/sG/sA/sSo before next tile's phase A
    }
}

extern "C" void kernel_launch(void* const* d_in, const int* in_sizes, int n_in,
                              void* d_out, int out_size) {
    const float* s      = (const float*)d_in[0];
    const float* v      = (const float*)d_in[1];
    const float* frames = (const float*)d_in[2];
    const float* Wd     = (const float*)d_in[3];
    const float* Wds    = (const float*)d_in[4];
    const float* bds    = (const float*)d_in[5];
    const float* Wu     = (const float*)d_in[6];
    const float* Wso    = (const float*)d_in[7];
    const float* bso    = (const float*)d_in[8];
    const float* Wg     = (const float*)d_in[9];
    const float* bg     = (const float*)d_in[10];
    float* out          = (float*)d_out;

    int dev = 0;
    cudaGetDevice(&dev);
    int smCount = 148;
    cudaDeviceGetAttribute(&smCount, cudaDevAttrMultiProcessorCount, dev);

    const size_t smem = (size_t)SMEM_FLOATS * sizeof(float);
    cudaFuncSetAttribute(fused_tpp_kernel,
                         cudaFuncAttributeMaxDynamicSharedMemorySize, (int)smem);
    fused_tpp_kernel<<<smCount, THREADS, smem>>>(s, v, frames, Wd, Wds, bds, Wu,
                                                 Wso, bso, Wg, bg, out);
}

// round 5
// speedup vs baseline: 1.1247x; 1.0523x over previous
#include <cuda_runtime.h>
#include <math.h>

typedef unsigned long long ull;

// Problem constants (fixed by dataset)
constexpr int N_ROWS  = 400000;
constexpr int TILE    = 64;
constexpr int THREADS = 512;
constexpr int NT      = N_ROWS / TILE;   // 6250
constexpr int KPAD    = 160;             // 153 padded with zero W rows
constexpr int WSO_STR = 164;             // transposed W_sout row stride (floats)
constexpr int WG_STR  = 132;             // transposed W_gate row stride (floats)

// Shared-memory float offsets
constexpr int OFF_WSO = 0;                         // [128][164] transposed, k-major
constexpr int OFF_WG  = OFF_WSO + 128 * WSO_STR;   // [64][132] transposed, k-major
constexpr int OFF_WD  = OFF_WG + 64 * WG_STR;      // [64][16]
constexpr int OFF_WU  = OFF_WD + 64 * 16;          // [16][64]
constexpr int OFF_WDS = OFF_WU + 16 * 64;          // [64][4] (col 3 pad)
constexpr int OFF_BSO = OFF_WDS + 64 * 4;          // [128]
constexpr int OFF_BG  = OFF_BSO + 128;             // [64]
constexpr int OFF_BDS = OFF_BG + 64;               // [4]
constexpr int OFF_A   = OFF_BDS + 4;               // [64][160] concat tile
constexpr int OFF_Z   = OFF_A + 64 * 160;          // [64][3][16]
constexpr int OFF_SO  = OFF_Z + 64 * 48;           // [64][128] s_out (pre-silu)
constexpr int OFF_G   = OFF_SO + 64 * 128;         // [64][64] gate (also vs scratch)
constexpr int SMEM_FLOATS = OFF_G + 64 * 64;       // 57540 floats = 230160 B

__device__ __forceinline__ float sigm(float x) { return 1.0f / (1.0f + __expf(-x)); }

__device__ __forceinline__ void fma2(ull& d, ull a, ull b) {
    asm("fma.rn.f32x2 %0, %1, %2, %0;" : "+l"(d) : "l"(a), "l"(b));
}
__device__ __forceinline__ float2 unpack2(ull x) {
    float2 r;
    asm("mov.b64 {%0, %1}, %2;" : "=f"(r.x), "=f"(r.y) : "l"(x));
    return r;
}

__global__ void __launch_bounds__(THREADS, 1)
fused_tpp_kernel(const float* __restrict__ gs, const float* __restrict__ gv,
                 const float* __restrict__ gframes,
                 const float* __restrict__ gWd, const float* __restrict__ gWds,
                 const float* __restrict__ gbds, const float* __restrict__ gWu,
                 const float* __restrict__ gWso, const float* __restrict__ gbso,
                 const float* __restrict__ gWg, const float* __restrict__ gbg,
                 float* __restrict__ out)
{
    extern __shared__ float sm[];
    float* sWsoT = sm + OFF_WSO;
    float* sWgT  = sm + OFF_WG;
    float* sWd   = sm + OFF_WD;
    float* sWu   = sm + OFF_WU;
    float* sWds  = sm + OFF_WDS;
    float* sbso  = sm + OFF_BSO;
    float* sbg   = sm + OFF_BG;
    float* sbds  = sm + OFF_BDS;
    float* sA    = sm + OFF_A;
    float* sZ    = sm + OFF_Z;
    float* sSo   = sm + OFF_SO;
    float* sG    = sm + OFF_G;

    const int tid = threadIdx.x;

    // ---- one-time weight staging (transposed for the two big GEMMs) ----
    for (int i = tid; i < 128 * KPAD; i += THREADS) {
        int c = i / KPAD, k = i % KPAD;
        sWsoT[c * WSO_STR + k] = (k < 153) ? gWso[k * 128 + c] : 0.0f;
    }
    for (int i = tid; i < 64 * 128; i += THREADS) {
        int c = i / 128, k = i % 128;
        sWgT[c * WG_STR + k] = gWg[k * 64 + c];
    }
    for (int i = tid; i < 64 * 16; i += THREADS) sWd[i] = gWd[i];
    for (int i = tid; i < 16 * 64; i += THREADS) sWu[i] = gWu[i];
    for (int i = tid; i < 64; i += THREADS) {
        sWds[i * 4 + 0] = gWds[i * 3 + 0];
        sWds[i * 4 + 1] = gWds[i * 3 + 1];
        sWds[i * 4 + 2] = gWds[i * 3 + 2];
        sWds[i * 4 + 3] = 0.0f;
    }
    if (tid < 128) sbso[tid] = gbso[tid];
    if (tid < 64)  sbg[tid]  = gbg[tid];
    if (tid < 4)   sbds[tid] = (tid < 3) ? gbds[tid] : 0.0f;
    // zero the permanently-unused concat pad columns 153..159 (once)
    for (int i = tid; i < TILE * 7; i += THREADS) {
        int r = i / 7, c = 153 + (i % 7);
        sA[r * 160 + c] = 0.0f;
    }
    __syncthreads();

    float* outS = out;
    float* outV = out + (size_t)N_ROWS * 128;

    for (int tile = blockIdx.x; tile < NT; tile += gridDim.x) {
        const int row0 = tile * TILE;

        // ---- Phase A1: stage s into concat cols [0,128) ----
        {
            const float4* sg4 = (const float4*)(gs + (size_t)row0 * 128);
            #pragma unroll
            for (int q = 0; q < 4; q++) {
                int i = tid + q * THREADS;               // 2048 float4s
                int r = i >> 5, c = i & 31;
                float4 x = sg4[r * 32 + c];
                *(float4*)&sA[r * 160 + c * 4] = x;
            }
        }

        // ---- Phase A2: z = v^T @ W_down (threads 0..255: 1 row, 4 h-cols, 3 f) ----
        if (tid < 256) {
            const int r = tid >> 2, j = tid & 3, h0 = j * 4;
            const float4* vr = (const float4*)(gv + (size_t)(row0 + r) * 192);
            float az[12];
            #pragma unroll
            for (int i = 0; i < 12; i++) az[i] = 0.0f;
            #pragma unroll 4
            for (int kc = 0; kc < 16; kc++) {
                float4 p0 = vr[kc * 3 + 0];
                float4 p1 = vr[kc * 3 + 1];
                float4 p2 = vr[kc * 3 + 2];
                float vk[4][3] = {{p0.x, p0.y, p0.z}, {p0.w, p1.x, p1.y},
                                  {p1.z, p1.w, p2.x}, {p2.y, p2.z, p2.w}};
                #pragma unroll
                for (int kk = 0; kk < 4; kk++) {
                    const int k = kc * 4 + kk;
                    float4 w = *(const float4*)&sWd[k * 16 + h0];
                    az[0] += vk[kk][0] * w.x; az[1]  += vk[kk][0] * w.y;
                    az[2] += vk[kk][0] * w.z; az[3]  += vk[kk][0] * w.w;
                    az[4] += vk[kk][1] * w.x; az[5]  += vk[kk][1] * w.y;
                    az[6] += vk[kk][1] * w.z; az[7]  += vk[kk][1] * w.w;
                    az[8] += vk[kk][2] * w.x; az[9]  += vk[kk][2] * w.y;
                    az[10]+= vk[kk][2] * w.z; az[11] += vk[kk][2] * w.w;
                }
            }
            #pragma unroll
            for (int i = 0; i < 4; i++) {
                float z0 = az[i], z1 = az[4 + i], z2 = az[8 + i];
                sZ[r * 48 + 0  + h0 + i] = z0;
                sZ[r * 48 + 16 + h0 + i] = z1;
                sZ[r * 48 + 32 + h0 + i] = z2;
                sA[r * 160 + 137 + h0 + i] = sqrtf(z0 * z0 + z1 * z1 + z2 * z2);
            }
        }

        // ---- Phase A3: vs = silu(v^T @ W_down_s + b) -> scratch (sG region) ----
        if (tid >= 256 && tid < 256 + TILE * 3) {
            const int t = tid - 256;
            const int r = t / 3, f = t % 3;
            const float* vr = gv + (size_t)(row0 + r) * 192;
            float a0 = 0.f, a1 = 0.f, a2 = 0.f;
            #pragma unroll 8
            for (int k = 0; k < 64; k++) {
                float vk = vr[k * 3 + f];
                a0 += vk * sWds[k * 4 + 0];
                a1 += vk * sWds[k * 4 + 1];
                a2 += vk * sWds[k * 4 + 2];
            }
            a0 += sbds[0]; a1 += sbds[1]; a2 += sbds[2];
            sG[r * 9 + f * 3 + 0] = a0 * sigm(a0);
            sG[r * 9 + f * 3 + 1] = a1 * sigm(a1);
            sG[r * 9 + f * 3 + 2] = a2 * sigm(a2);
        }
        __syncthreads();

        // ---- Phase A4: scalarized = frames @ vs -> concat cols [128,137) ----
        if (tid < TILE * 3) {
            const int r = tid / 3, f = tid % 3;
            const float* fr = gframes + (size_t)(row0 + r) * 9 + f * 3;
            float f0 = fr[0], f1 = fr[1], f2 = fr[2];
            #pragma unroll
            for (int d = 0; d < 3; d++) {
                float val = f0 * sG[r * 9 + 0 + d] + f1 * sG[r * 9 + 3 + d] +
                            f2 * sG[r * 9 + 6 + d];
                sA[r * 160 + 128 + f * 3 + d] = val;
            }
        }
        __syncthreads();

        // ---- Phase B: s_out = concat @ W_sout + b (f32x2, k-pair packed) ----
        // 16 warps x 4 rows; lane cg covers cols {cg, cg+32, cg+64, cg+96}
        {
            const int rg = tid >> 5, cg = tid & 31;
            const int r0 = rg * 4;
            ull acc[4][4];
            #pragma unroll
            for (int i = 0; i < 4; i++)
                #pragma unroll
                for (int j = 0; j < 4; j++) acc[i][j] = 0ULL;
            #pragma unroll 2
            for (int k = 0; k < KPAD; k += 4) {
                ulonglong2 w[4];
                #pragma unroll
                for (int j = 0; j < 4; j++)
                    w[j] = *(const ulonglong2*)&sWsoT[(cg + 32 * j) * WSO_STR + k];
                #pragma unroll
                for (int i = 0; i < 4; i++) {
                    ulonglong2 a2 = *(const ulonglong2*)&sA[(r0 + i) * 160 + k];
                    #pragma unroll
                    for (int j = 0; j < 4; j++) {
                        fma2(acc[i][j], a2.x, w[j].x);
                        fma2(acc[i][j], a2.y, w[j].y);
                    }
                }
            }
            #pragma unroll
            for (int i = 0; i < 4; i++) {
                #pragma unroll
                for (int j = 0; j < 4; j++) {
                    const int c = cg + 32 * j;
                    float2 p = unpack2(acc[i][j]);
                    sSo[(r0 + i) * 128 + c] = p.x + p.y + sbso[c];
                }
            }
        }
        __syncthreads();

        // ---- Phase B2: silu(s_out) -> global (vectorized) ----
        {
            #pragma unroll
            for (int q = 0; q < 4; q++) {
                const int idx = tid + q * THREADS;      // 2048 quads
                const int r = idx >> 5, c4 = (idx & 31) * 4;
                float4 so = *(const float4*)&sSo[r * 128 + c4];
                float4 o;
                o.x = so.x * sigm(so.x); o.y = so.y * sigm(so.y);
                o.z = so.z * sigm(so.z); o.w = so.w * sigm(so.w);
                *(float4*)&outS[(size_t)(row0 + r) * 128 + c4] = o;
            }
        }

        // ---- Phase C: gate = sigmoid(s_out @ W_gate + b) (f32x2) ----
        // 16 warps x 4 rows; lane cg covers cols {cg, cg+32}
        {
            const int rg = tid >> 5, cg = tid & 31;
            const int r0 = rg * 4;
            ull acc[4][2];
            #pragma unroll
            for (int i = 0; i < 4; i++) { acc[i][0] = 0ULL; acc[i][1] = 0ULL; }
            #pragma unroll 2
            for (int k = 0; k < 128; k += 4) {
                ulonglong2 w0 = *(const ulonglong2*)&sWgT[cg * WG_STR + k];
                ulonglong2 w1 = *(const ulonglong2*)&sWgT[(cg + 32) * WG_STR + k];
                #pragma unroll
                for (int i = 0; i < 4; i++) {
                    ulonglong2 a2 = *(const ulonglong2*)&sSo[(r0 + i) * 128 + k];
                    fma2(acc[i][0], a2.x, w0.x);
                    fma2(acc[i][0], a2.y, w0.y);
                    fma2(acc[i][1], a2.x, w1.x);
                    fma2(acc[i][1], a2.y, w1.y);
                }
            }
            #pragma unroll
            for (int i = 0; i < 4; i++) {
                #pragma unroll
                for (int j = 0; j < 2; j++) {
                    const int c = cg + 32 * j;
                    float2 p = unpack2(acc[i][j]);
                    sG[(r0 + i) * 64 + c] = sigm(p.x + p.y + sbg[c]);
                }
            }
        }
        __syncthreads();

        // ---- Phase D: v_up = z @ W_up ; v_out[o][f] = v_up[f][o] * gate[o] ----
        // 512 threads: 1 row each (tid>>3), 8 out cols (tid&7)*8
        {
            const int r = tid >> 3, j = tid & 7, o0 = j * 8;
            float z[3][16];
            #pragma unroll
            for (int f = 0; f < 3; f++)
                #pragma unroll
                for (int q = 0; q < 4; q++) {
                    float4 zz = *(const float4*)&sZ[r * 48 + f * 16 + q * 4];
                    z[f][q * 4 + 0] = zz.x; z[f][q * 4 + 1] = zz.y;
                    z[f][q * 4 + 2] = zz.z; z[f][q * 4 + 3] = zz.w;
                }
            float g[8];
            #pragma unroll
            for (int q = 0; q < 2; q++) {
                float4 gg = *(const float4*)&sG[r * 64 + o0 + q * 4];
                g[q * 4 + 0] = gg.x; g[q * 4 + 1] = gg.y;
                g[q * 4 + 2] = gg.z; g[q * 4 + 3] = gg.w;
            }
            float* ov = outV + (size_t)(row0 + r) * 192 + o0 * 3;
            #pragma unroll
            for (int oq = 0; oq < 2; oq++) {
                float acc[3][4];
                #pragma unroll
                for (int f = 0; f < 3; f++)
                    #pragma unroll
                    for (int m = 0; m < 4; m++) acc[f][m] = 0.0f;
                #pragma unroll
                for (int h = 0; h < 16; h++) {
                    float4 w = *(const float4*)&sWu[h * 64 + o0 + oq * 4];
                    acc[0][0] += z[0][h] * w.x; acc[0][1] += z[0][h] * w.y;
                    acc[0][2] += z[0][h] * w.z; acc[0][3] += z[0][h] * w.w;
                    acc[1][0] += z[1][h] * w.x; acc[1][1] += z[1][h] * w.y;
                    acc[1][2] += z[1][h] * w.z; acc[1][3] += z[1][h] * w.w;
                    acc[2][0] += z[2][h] * w.x; acc[2][1] += z[2][h] * w.y;
                    acc[2][2] += z[2][h] * w.z; acc[2][3] += z[2][h] * w.w;
                }
                float vals[12];
                #pragma unroll
                for (int m = 0; m < 4; m++) {
                    float gm = g[oq * 4 + m];
                    vals[m * 3 + 0] = acc[0][m] * gm;
                    vals[m * 3 + 1] = acc[1][m] * gm;
                    vals[m * 3 + 2] = acc[2][m] * gm;
                }
                float4 t0 = {vals[0], vals[1], vals[2],  vals[3]};
                float4 t1 = {vals[4], vals[5], vals[6],  vals[7]};
                float4 t2 = {vals[8], vals[9], vals[10], vals[11]};
                *(float4*)(ov + oq * 12 + 0) = t0;
                *(float4*)(ov + oq * 12 + 4) = t1;
                *(float4*)(ov + oq * 12 + 8) = t2;
            }
        }
        __syncthreads();   // protect sZ/sG/sA/sSo before next tile's phase A
    }
}

extern "C" void kernel_launch(void* const* d_in, const int* in_sizes, int n_in,
                              void* d_out, int out_size) {
    const float* s      = (const float*)d_in[0];
    const float* v      = (const float*)d_in[1];
    const float* frames = (const float*)d_in[2];
    const float* Wd     = (const float*)d_in[3];
    const float* Wds    = (const float*)d_in[4];
    const float* bds    = (const float*)d_in[5];
    const float* Wu     = (const float*)d_in[6];
    const float* Wso    = (const float*)d_in[7];
    const float* bso    = (const float*)d_in[8];
    const float* Wg     = (const float*)d_in[9];
    const float* bg     = (const float*)d_in[10];
    float* out          = (float*)d_out;

    int dev = 0;
    cudaGetDevice(&dev);
    int smCount = 148;
    cudaDeviceGetAttribute(&smCount, cudaDevAttrMultiProcessorCount, dev);

    const size_t smem = (size_t)SMEM_FLOATS * sizeof(float);
    cudaFuncSetAttribute(fused_tpp_kernel,
                         cudaFuncAttributeMaxDynamicSharedMemorySize, (int)smem);
    fused_tpp_kernel<<<smCount, THREADS, smem>>>(s, v, frames, Wd, Wds, bds, Wu,
                                                 Wso, bso, Wg, bg, out);
}

// round 7
// speedup vs baseline: 1.1266x; 1.0017x over previous
#include <cuda_runtime.h>
#include <math.h>

typedef unsigned long long ull;

constexpr int N_ROWS  = 400000;
constexpr int TILE    = 64;
constexpr int THREADS = 512;
constexpr int NT      = N_ROWS / TILE;   // 6250
constexpr int KPAD    = 160;
constexpr int A_STR   = 164;   // sA & WsoT stride  (bank step 4/row)
constexpr int SO_STR  = 132;   // sSo & WgT stride  (bank step 4/row)
constexpr int G_STR   = 68;    // gate stride

// smem float offsets
constexpr int OFF_WSO = 0;                        // [128 cols][164 k]
constexpr int OFF_WG  = OFF_WSO + 128 * A_STR;    // [64 cols][132 k]
constexpr int OFF_WD  = OFF_WG + 64 * SO_STR;     // [64][16]
constexpr int OFF_WU  = OFF_WD + 1024;            // [16][64]
constexpr int OFF_WDS = OFF_WU + 1024;            // [64][4]
constexpr int OFF_BSO = OFF_WDS + 256;            // [128]
constexpr int OFF_BG  = OFF_BSO + 128;            // [64]
constexpr int OFF_BDS = OFF_BG + 64;              // [4]
constexpr int OFF_A   = OFF_BDS + 4;              // [64][164] concat; sSo [64][132] overlaid here
constexpr int OFF_Z   = OFF_A + 64 * A_STR;       // [64][48]
constexpr int OFF_G   = OFF_Z + 64 * 48;          // [64][68] gate (also vs scratch)
constexpr int SMEM_FLOATS = OFF_G + 64 * G_STR;   // 49860 floats = 199440 B

__device__ __forceinline__ float sigm(float x) { return 1.0f / (1.0f + __expf(-x)); }
__device__ __forceinline__ void fma2(ull& d, ull a, ull b) {
    asm("fma.rn.f32x2 %0, %1, %2, %0;" : "+l"(d) : "l"(a), "l"(b));
}
__device__ __forceinline__ float2 unpack2(ull x) {
    float2 r;
    asm("mov.b64 {%0, %1}, %2;" : "=f"(r.x), "=f"(r.y) : "l"(x));
    return r;
}

__global__ void __launch_bounds__(THREADS, 1)
fused_tpp_kernel(const float* __restrict__ gs, const float* __restrict__ gv,
                 const float* __restrict__ gframes,
                 const float* __restrict__ gWd, const float* __restrict__ gWds,
                 const float* __restrict__ gbds, const float* __restrict__ gWu,
                 const float* __restrict__ gWso, const float* __restrict__ gbso,
                 const float* __restrict__ gWg, const float* __restrict__ gbg,
                 float* __restrict__ out)
{
    extern __shared__ float sm[];
    float* sWsoT = sm + OFF_WSO;
    float* sWgT  = sm + OFF_WG;
    float* sWd   = sm + OFF_WD;
    float* sWu   = sm + OFF_WU;
    float* sWds  = sm + OFF_WDS;
    float* sbso  = sm + OFF_BSO;
    float* sbg   = sm + OFF_BG;
    float* sbds  = sm + OFF_BDS;
    float* sA    = sm + OFF_A;           // concat tile, stride A_STR
    float* sSo   = sm + OFF_A;           // OVERLAY: s_out tile, stride SO_STR
    float* sZ    = sm + OFF_Z;
    float* sG    = sm + OFF_G;

    const int tid  = threadIdx.x;
    const int wid  = tid >> 5;
    const int lane = tid & 31;
    const int cl   = lane & 7;           // 8 col-lanes
    const int rl   = lane >> 3;          // 4 row-lanes

    // ---- one-time weight staging (transposed, padded strides) ----
    for (int i = tid; i < 128 * A_STR; i += THREADS) {
        int c = i / A_STR, k = i % A_STR;
        sWsoT[i] = (k < 153) ? gWso[k * 128 + c] : 0.0f;
    }
    for (int i = tid; i < 64 * SO_STR; i += THREADS) {
        int c = i / SO_STR, k = i % SO_STR;
        sWgT[i] = (k < 128) ? gWg[k * 64 + c] : 0.0f;
    }
    for (int i = tid; i < 64 * 16; i += THREADS) sWd[i] = gWd[i];
    for (int i = tid; i < 16 * 64; i += THREADS) sWu[i] = gWu[i];
    if (tid < 64) {
        sWds[tid * 4 + 0] = gWds[tid * 3 + 0];
        sWds[tid * 4 + 1] = gWds[tid * 3 + 1];
        sWds[tid * 4 + 2] = gWds[tid * 3 + 2];
        sWds[tid * 4 + 3] = 0.0f;
    }
    if (tid < 128) sbso[tid] = gbso[tid];
    if (tid < 64)  sbg[tid]  = gbg[tid];
    if (tid < 4)   sbds[tid] = (tid < 3) ? gbds[tid] : 0.0f;
    __syncthreads();

    float* outS = out;
    float* outV = out + (size_t)N_ROWS * 128;

    for (int tile = blockIdx.x; tile < NT; tile += gridDim.x) {
        const int row0 = tile * TILE;

        // ---- A1: stage s into cols [0,128); re-zero pad cols 153..159 ----
        {
            const float4* sg4 = (const float4*)(gs + (size_t)row0 * 128);
            #pragma unroll
            for (int q = 0; q < 4; q++) {
                int i = tid + q * THREADS;               // 2048 float4s
                int r = i >> 5, c = i & 31;
                float4 x = sg4[r * 32 + c];
                *(float4*)&sA[r * A_STR + c * 4] = x;
            }
            if (tid < 448) {                             // 64 rows x 7 pad cols
                int r = tid / 7, c = 153 + tid % 7;
                sA[r * A_STR + c] = 0.0f;
            }
        }

        // ---- A2: z = v^T @ W_down (threads 0..255) ----
        if (tid < 256) {
            const int r = tid >> 2, j = tid & 3, h0 = j * 4;
            const float4* vr = (const float4*)(gv + (size_t)(row0 + r) * 192);
            float az[12];
            #pragma unroll
            for (int i = 0; i < 12; i++) az[i] = 0.0f;
            #pragma unroll 4
            for (int kc = 0; kc < 16; kc++) {
                float4 p0 = vr[kc * 3 + 0];
                float4 p1 = vr[kc * 3 + 1];
                float4 p2 = vr[kc * 3 + 2];
                float vk[4][3] = {{p0.x, p0.y, p0.z}, {p0.w, p1.x, p1.y},
                                  {p1.z, p1.w, p2.x}, {p2.y, p2.z, p2.w}};
                #pragma unroll
                for (int kk = 0; kk < 4; kk++) {
                    const int k = kc * 4 + kk;
                    float4 w = *(const float4*)&sWd[k * 16 + h0];
                    az[0] += vk[kk][0] * w.x; az[1]  += vk[kk][0] * w.y;
                    az[2] += vk[kk][0] * w.z; az[3]  += vk[kk][0] * w.w;
                    az[4] += vk[kk][1] * w.x; az[5]  += vk[kk][1] * w.y;
                    az[6] += vk[kk][1] * w.z; az[7]  += vk[kk][1] * w.w;
                    az[8] += vk[kk][2] * w.x; az[9]  += vk[kk][2] * w.y;
                    az[10]+= vk[kk][2] * w.z; az[11] += vk[kk][2] * w.w;
                }
            }
            #pragma unroll
            for (int i = 0; i < 4; i++) {
                float z0 = az[i], z1 = az[4 + i], z2 = az[8 + i];
                sZ[r * 48 + 0  + h0 + i] = z0;
                sZ[r * 48 + 16 + h0 + i] = z1;
                sZ[r * 48 + 32 + h0 + i] = z2;
                sA[r * A_STR + 137 + h0 + i] = sqrtf(z0 * z0 + z1 * z1 + z2 * z2);
            }
        }

        // ---- A3: vs = silu(v^T @ W_down_s + b) -> sG scratch ----
        if (tid >= 256 && tid < 256 + TILE * 3) {
            const int t = tid - 256;
            const int r = t / 3, f = t % 3;
            const float* vr = gv + (size_t)(row0 + r) * 192;
            float a0 = 0.f, a1 = 0.f, a2 = 0.f;
            #pragma unroll 8
            for (int k = 0; k < 64; k++) {
                float vk = vr[k * 3 + f];
                a0 += vk * sWds[k * 4 + 0];
                a1 += vk * sWds[k * 4 + 1];
                a2 += vk * sWds[k * 4 + 2];
            }
            a0 += sbds[0]; a1 += sbds[1]; a2 += sbds[2];
            sG[r * 9 + f * 3 + 0] = a0 * sigm(a0);
            sG[r * 9 + f * 3 + 1] = a1 * sigm(a1);
            sG[r * 9 + f * 3 + 2] = a2 * sigm(a2);
        }
        __syncthreads();

        // ---- A4: scalarized = frames @ vs -> cols [128,137) ----
        if (tid < TILE * 3) {
            const int r = tid / 3, f = tid % 3;
            const float* fr = gframes + (size_t)(row0 + r) * 9 + f * 3;
            float f0 = fr[0], f1 = fr[1], f2 = fr[2];
            #pragma unroll
            for (int d = 0; d < 3; d++) {
                float val = f0 * sG[r * 9 + 0 + d] + f1 * sG[r * 9 + 3 + d] +
                            f2 * sG[r * 9 + 6 + d];
                sA[r * A_STR + 128 + f * 3 + d] = val;
            }
        }
        __syncthreads();

        // ---- Phase B: s_out = concat @ Wso (balanced 16x32 warp tiles) ----
        // warp: rg=wid&3 rows rg*16..+16, cg=wid>>2 cols cg*32..+32
        // lane: rows rg*16+rl+4i (i<4), cols cg*32+cl+8j (j<4)
        ull acc[4][4];
        {
            const int rg = wid & 3, cg = wid >> 2;
            const float* ap = sA + (rg * 16 + rl) * A_STR;
            const float* wp = sWsoT + (cg * 32 + cl) * A_STR;
            #pragma unroll
            for (int i = 0; i < 4; i++)
                #pragma unroll
                for (int j = 0; j < 4; j++) acc[i][j] = 0ULL;
            #pragma unroll 4
            for (int k = 0; k < KPAD; k += 4) {
                ulonglong2 w[4], a[4];
                #pragma unroll
                for (int j = 0; j < 4; j++)
                    w[j] = *(const ulonglong2*)&wp[(8 * j) * A_STR + k];
                #pragma unroll
                for (int i = 0; i < 4; i++)
                    a[i] = *(const ulonglong2*)&ap[(4 * i) * A_STR + k];
                #pragma unroll
                for (int i = 0; i < 4; i++)
                    #pragma unroll
                    for (int j = 0; j < 4; j++) {
                        fma2(acc[i][j], a[i].x, w[j].x);
                        fma2(acc[i][j], a[i].y, w[j].y);
                    }
            }
        }
        __syncthreads();   // all sA reads done before overlay writes

        // ---- B epilogue: write s_out into sSo (overlay on sA) ----
        {
            const int rg = wid & 3, cg = wid >> 2;
            #pragma unroll
            for (int i = 0; i < 4; i++) {
                const int r = rg * 16 + rl + 4 * i;
                #pragma unroll
                for (int j = 0; j < 4; j++) {
                    const int c = cg * 32 + cl + 8 * j;
                    float2 p = unpack2(acc[i][j]);
                    sSo[r * SO_STR + c] = p.x + p.y + sbso[c];
                }
            }
        }
        __syncthreads();

        // ---- B2: silu(s_out) -> global ----
        {
            #pragma unroll
            for (int q = 0; q < 4; q++) {
                const int idx = tid + q * THREADS;      // 2048 quads
                const int r = idx >> 5, c4 = (idx & 31) * 4;
                float4 so = *(const float4*)&sSo[r * SO_STR + c4];
                float4 o;
                o.x = so.x * sigm(so.x); o.y = so.y * sigm(so.y);
                o.z = so.z * sigm(so.z); o.w = so.w * sigm(so.w);
                *(float4*)&outS[(size_t)(row0 + r) * 128 + c4] = o;
            }
        }

        // ---- Phase C: gate = sigmoid(s_out @ Wg) (balanced 16x16 warp tiles) ----
        // lane: rows rg*16+rl+4i (i<4), cols cg*16+cl+8j (j<2)
        {
            const int rg = wid & 3, cg = wid >> 2;
            const float* ap = sSo + (rg * 16 + rl) * SO_STR;
            const float* wp = sWgT + (cg * 16 + cl) * SO_STR;
            ull c2[4][2];
            #pragma unroll
            for (int i = 0; i < 4; i++) { c2[i][0] = 0ULL; c2[i][1] = 0ULL; }
            #pragma unroll 4
            for (int k = 0; k < 128; k += 4) {
                ulonglong2 w0 = *(const ulonglong2*)&wp[k];
                ulonglong2 w1 = *(const ulonglong2*)&wp[8 * SO_STR + k];
                #pragma unroll
                for (int i = 0; i < 4; i++) {
                    ulonglong2 a2 = *(const ulonglong2*)&ap[(4 * i) * SO_STR + k];
                    fma2(c2[i][0], a2.x, w0.x);
                    fma2(c2[i][0], a2.y, w0.y);
                    fma2(c2[i][1], a2.x, w1.x);
                    fma2(c2[i][1], a2.y, w1.y);
                }
            }
            #pragma unroll
            for (int i = 0; i < 4; i++) {
                const int r = rg * 16 + rl + 4 * i;
                #pragma unroll
                for (int j = 0; j < 2; j++) {
                    const int c = cg * 16 + cl + 8 * j;
                    float2 p = unpack2(c2[i][j]);
                    sG[r * G_STR + c] = sigm(p.x + p.y + sbg[c]);
                }
            }
        }
        __syncthreads();

        // ---- Phase D: v_up = z @ W_up ; v_out = v_up^T * gate ----
        {
            const int r = tid >> 3, j = tid & 7, o0 = j * 8;
            float z[3][16];
            #pragma unroll
            for (int f = 0; f < 3; f++)
                #pragma unroll
                for (int q = 0; q < 4; q++) {
                    float4 zz = *(const float4*)&sZ[r * 48 + f * 16 + q * 4];
                    z[f][q * 4 + 0] = zz.x; z[f][q * 4 + 1] = zz.y;
                    z[f][q * 4 + 2] = zz.z; z[f][q * 4 + 3] = zz.w;
                }
            float g[8];
            #pragma unroll
            for (int q = 0; q < 2; q++) {
                float4 gg = *(const float4*)&sG[r * G_STR + o0 + q * 4];
                g[q * 4 + 0] = gg.x; g[q * 4 + 1] = gg.y;
                g[q * 4 + 2] = gg.z; g[q * 4 + 3] = gg.w;
            }
            float* ov = outV + (size_t)(row0 + r) * 192 + o0 * 3;
            #pragma unroll
            for (int oq = 0; oq < 2; oq++) {
                float acc3[3][4];
                #pragma unroll
                for (int f = 0; f < 3; f++)
                    #pragma unroll
                    for (int m = 0; m < 4; m++) acc3[f][m] = 0.0f;
                #pragma unroll
                for (int h = 0; h < 16; h++) {
                    float4 w = *(const float4*)&sWu[h * 64 + o0 + oq * 4];
                    acc3[0][0] += z[0][h] * w.x; acc3[0][1] += z[0][h] * w.y;
                    acc3[0][2] += z[0][h] * w.z; acc3[0][3] += z[0][h] * w.w;
                    acc3[1][0] += z[1][h] * w.x; acc3[1][1] += z[1][h] * w.y;
                    acc3[1][2] += z[1][h] * w.z; acc3[1][3] += z[1][h] * w.w;
                    acc3[2][0] += z[2][h] * w.x; acc3[2][1] += z[2][h] * w.y;
                    acc3[2][2] += z[2][h] * w.z; acc3[2][3] += z[2][h] * w.w;
                }
                float vals[12];
                #pragma unroll
                for (int m = 0; m < 4; m++) {
                    float gm = g[oq * 4 + m];
                    vals[m * 3 + 0] = acc3[0][m] * gm;
                    vals[m * 3 + 1] = acc3[1][m] * gm;
                    vals[m * 3 + 2] = acc3[2][m] * gm;
                }
                float4 t0 = {vals[0], vals[1], vals[2],  vals[3]};
                float4 t1 = {vals[4], vals[5], vals[6],  vals[7]};
                float4 t2 = {vals[8], vals[9], vals[10], vals[11]};
                *(float4*)(ov + oq * 12 + 0) = t0;
                *(float4*)(ov + oq * 12 + 4) = t1;
                *(float4*)(ov + oq * 12 + 8) = t2;
            }
        }
        __syncthreads();   // protect sZ/sG/sA before next tile
    }
}

extern "C" void kernel_launch(void* const* d_in, const int* in_sizes, int n_in,
                              void* d_out, int out_size) {
    const float* s      = (const float*)d_in[0];
    const float* v      = (const float*)d_in[1];
    const float* frames = (const float*)d_in[2];
    const float* Wd     = (const float*)d_in[3];
    const float* Wds    = (const float*)d_in[4];
    const float* bds    = (const float*)d_in[5];
    const float* Wu     = (const float*)d_in[6];
    const float* Wso    = (const float*)d_in[7];
    const float* bso    = (const float*)d_in[8];
    const float* Wg     = (const float*)d_in[9];
    const float* bg     = (const float*)d_in[10];
    float* out          = (float*)d_out;

    int dev = 0;
    cudaGetDevice(&dev);
    int smCount = 148;
    cudaDeviceGetAttribute(&smCount, cudaDevAttrMultiProcessorCount, dev);

    const size_t smem = (size_t)SMEM_FLOATS * sizeof(float);
    cudaFuncSetAttribute(fused_tpp_kernel,
                         cudaFuncAttributeMaxDynamicSharedMemorySize, (int)smem);
    fused_tpp_kernel<<<smCount, THREADS, smem>>>(s, v, frames, Wd, Wds, bds, Wu,
                                                 Wso, bso, Wg, bg, out);
}

// round 9
// speedup vs baseline: 1.3264x; 1.1773x over previous
#include <cuda_runtime.h>
#include <cuda_bf16.h>
#include <stdint.h>
#include <math.h>

constexpr int N_ROWS  = 400000;
constexpr int TILE    = 64;
constexpr int THREADS = 512;
constexpr int NT      = N_ROWS / TILE;   // 6250

constexpr int KSTR = 168;                // bf16 k-stride (168/2 mod 32 = 20 -> conflict-free frags)
constexpr int GSTR = 68;                 // gate f32 stride

// smem byte offsets
constexpr int OFF_WH  = 0;                         // 64512: W_hi bf16 [192][168]
constexpr int OFF_WL  = OFF_WH + 192 * KSTR * 2;   // 64512
constexpr int OFF_AH  = OFF_WL + 192 * KSTR * 2;   // 21504: A_hi bf16 [64][168]
constexpr int OFF_AL  = OFF_AH + 64 * KSTR * 2;    // 21504
constexpr int OFF_Z   = OFF_AL + 64 * KSTR * 2;    // 13312: z f32 [64][52]
constexpr int OFF_G   = OFF_Z + 64 * 52 * 4;       // 17408: gate f32 [64][68]
constexpr int OFF_VS  = OFF_G + 64 * GSTR * 4;     // 3072:  vs f32 [64][12]
constexpr int OFF_WD  = OFF_VS + 64 * 12 * 4;      // 4096
constexpr int OFF_WU  = OFF_WD + 4096;             // 4096
constexpr int OFF_WDS = OFF_WU + 4096;             // 1024
constexpr int OFF_BSO = OFF_WDS + 1024;            // 512
constexpr int OFF_BF  = OFF_BSO + 512;             // 256
constexpr int OFF_BDS = OFF_BF + 256;              // 16
constexpr int SMEM_BYTES = OFF_BDS + 64;           // ~215 KB

__device__ __forceinline__ float sigm(float x) { return 1.0f / (1.0f + __expf(-x)); }

__device__ __forceinline__ uint32_t bf2(float a, float b) {
    __nv_bfloat162 h; h.x = __float2bfloat16(a); h.y = __float2bfloat16(b);
    return *reinterpret_cast<uint32_t*>(&h);
}
__device__ __forceinline__ uint32_t bf2hi(float a, float b, float& la, float& lb) {
    __nv_bfloat16 ha = __float2bfloat16(a), hb = __float2bfloat16(b);
    la = a - __bfloat162float(ha);
    lb = b - __bfloat162float(hb);
    __nv_bfloat162 h; h.x = ha; h.y = hb;
    return *reinterpret_cast<uint32_t*>(&h);
}
__device__ __forceinline__ void mma16816(float* c, uint32_t a0, uint32_t a1, uint32_t a2,
                                         uint32_t a3, uint32_t b0, uint32_t b1) {
    asm volatile(
        "mma.sync.aligned.m16n8k16.row.col.f32.bf16.bf16.f32 "
        "{%0,%1,%2,%3}, {%4,%5,%6,%7}, {%8,%9}, {%0,%1,%2,%3};"
        : "+f"(c[0]), "+f"(c[1]), "+f"(c[2]), "+f"(c[3])
        : "r"(a0), "r"(a1), "r"(a2), "r"(a3), "r"(b0), "r"(b1));
}

__global__ void __launch_bounds__(THREADS, 1)
fused_tpp_mma(const float* __restrict__ gs, const float* __restrict__ gv,
              const float* __restrict__ gframes,
              const float* __restrict__ gWd, const float* __restrict__ gWds,
              const float* __restrict__ gbds, const float* __restrict__ gWu,
              const float* __restrict__ gWso, const float* __restrict__ gbso,
              const float* __restrict__ gWg, const float* __restrict__ gbg,
              float* __restrict__ out)
{
    extern __shared__ char smem[];
    float* sZ   = (float*)(smem + OFF_Z);
    float* gate = (float*)(smem + OFF_G);
    float* sVs  = (float*)(smem + OFF_VS);
    float* sWd  = (float*)(smem + OFF_WD);
    float* sWu  = (float*)(smem + OFF_WU);
    float* sWds = (float*)(smem + OFF_WDS);
    float* sbso = (float*)(smem + OFF_BSO);
    float* sbf  = (float*)(smem + OFF_BF);
    float* sbds = (float*)(smem + OFF_BDS);

    const int tid  = threadIdx.x;
    const int wid  = tid >> 5;
    const int lane = tid & 31;
    const int g    = lane >> 2;           // fragment group 0..7
    const int t    = lane & 3;            // thread-in-group

    // ---- one-time staging ----
    for (int i = tid; i < 64 * 16; i += THREADS) sWd[i] = gWd[i];
    for (int i = tid; i < 16 * 64; i += THREADS) sWu[i] = gWu[i];
    if (tid < 64) {
        sWds[tid * 4 + 0] = gWds[tid * 3 + 0];
        sWds[tid * 4 + 1] = gWds[tid * 3 + 1];
        sWds[tid * 4 + 2] = gWds[tid * 3 + 2];
        sWds[tid * 4 + 3] = 0.0f;
    }
    if (tid < 128) sbso[tid] = gbso[tid];
    if (tid < 4)   sbds[tid] = (tid < 3) ? gbds[tid] : 0.0f;
    if (tid < 64) {
        float acc = gbg[tid];
        for (int j = 0; j < 128; j++) acc += gbso[j] * gWg[j * 64 + tid];
        sbf[tid] = acc;
    }
    // fused gate weight Wf[k][n] = sum_j Wso[k][j]*Wg[j][n]  (scratch in A region)
    float* wf = (float*)(smem + OFF_AH);   // [153][64]
    for (int idx = tid; idx < 153 * 64; idx += THREADS) {
        int k = idx >> 6, n = idx & 63;
        float acc = 0.f;
        #pragma unroll 4
        for (int j = 0; j < 128; j++) acc += gWso[k * 128 + j] * gWg[j * 64 + n];
        wf[idx] = acc;
    }
    __syncthreads();
    // W_hi / W_lo: [192 n][KSTR k] bf16, rows n<128 = Wso col n, n>=128 = Wf col n-128
    for (int i = tid; i < 192 * KSTR; i += THREADS) {
        int n = i / KSTR, k = i % KSTR;
        float w = 0.f;
        if (k < 153) w = (n < 128) ? gWso[k * 128 + n] : wf[k * 64 + (n - 128)];
        __nv_bfloat16 h = __float2bfloat16(w);
        *(__nv_bfloat16*)(smem + OFF_WH + i * 2) = h;
        *(__nv_bfloat16*)(smem + OFF_WL + i * 2) = __float2bfloat16(w - __bfloat162float(h));
    }
    __syncthreads();
    // zero A_hi + A_lo (pads 153..167 stay zero forever)
    for (int i = tid; i < (2 * 64 * KSTR * 2) / 4; i += THREADS)
        ((uint32_t*)(smem + OFF_AH))[i] = 0;
    __syncthreads();

    float* outS = out;
    float* outV = out + (size_t)N_ROWS * 128;

    for (int tile = blockIdx.x; tile < NT; tile += gridDim.x) {
        const int row0 = tile * TILE;

        // ---- A1: s -> A_hi/A_lo slots 0..127 (tid>>3 = row, tid&7 = 16-col group) ----
        {
            const int rr = tid >> 3, c0 = (tid & 7) * 16;
            const float4* sr = (const float4*)(gs + (size_t)(row0 + rr) * 128 + c0);
            char* ah = smem + OFF_AH + rr * (KSTR * 2) + c0 * 2;
            char* al = smem + OFF_AL + rr * (KSTR * 2) + c0 * 2;
            #pragma unroll
            for (int q = 0; q < 4; q++) {
                float4 x = sr[q];
                float la, lb, lc, ld;
                uint32_t h0 = bf2hi(x.x, x.y, la, lb);
                uint32_t h1 = bf2hi(x.z, x.w, lc, ld);
                *(uint32_t*)(ah + q * 8)     = h0;
                *(uint32_t*)(ah + q * 8 + 4) = h1;
                *(uint32_t*)(al + q * 8)     = bf2(la, lb);
                *(uint32_t*)(al + q * 8 + 4) = bf2(lc, ld);
            }
        }

        // ---- A2: z = v^T W_down ; norms -> slots 137..152 ----
        if (tid < 256) {
            const int r = tid >> 2, j = tid & 3, h0 = j * 4;
            const float4* vr = (const float4*)(gv + (size_t)(row0 + r) * 192);
            float az[12];
            #pragma unroll
            for (int i = 0; i < 12; i++) az[i] = 0.0f;
            #pragma unroll 4
            for (int kc = 0; kc < 16; kc++) {
                float4 p0 = vr[kc * 3 + 0];
                float4 p1 = vr[kc * 3 + 1];
                float4 p2 = vr[kc * 3 + 2];
                float vk[4][3] = {{p0.x, p0.y, p0.z}, {p0.w, p1.x, p1.y},
                                  {p1.z, p1.w, p2.x}, {p2.y, p2.z, p2.w}};
                #pragma unroll
                for (int kk = 0; kk < 4; kk++) {
                    const int k = kc * 4 + kk;
                    float4 w = *(const float4*)&sWd[k * 16 + h0];
                    az[0] += vk[kk][0] * w.x; az[1]  += vk[kk][0] * w.y;
                    az[2] += vk[kk][0] * w.z; az[3]  += vk[kk][0] * w.w;
                    az[4] += vk[kk][1] * w.x; az[5]  += vk[kk][1] * w.y;
                    az[6] += vk[kk][1] * w.z; az[7]  += vk[kk][1] * w.w;
                    az[8] += vk[kk][2] * w.x; az[9]  += vk[kk][2] * w.y;
                    az[10]+= vk[kk][2] * w.z; az[11] += vk[kk][2] * w.w;
                }
            }
            #pragma unroll
            for (int i = 0; i < 4; i++) {
                float z0 = az[i], z1 = az[4 + i], z2 = az[8 + i];
                sZ[r * 52 + 0  + h0 + i] = z0;
                sZ[r * 52 + 16 + h0 + i] = z1;
                sZ[r * 52 + 32 + h0 + i] = z2;
                float nr = sqrtf(z0 * z0 + z1 * z1 + z2 * z2);
                __nv_bfloat16 h = __float2bfloat16(nr);
                const int slot = 137 + h0 + i;
                *(__nv_bfloat16*)(smem + OFF_AH + (r * KSTR + slot) * 2) = h;
                *(__nv_bfloat16*)(smem + OFF_AL + (r * KSTR + slot) * 2) =
                    __float2bfloat16(nr - __bfloat162float(h));
            }
        }

        // ---- A3: vs = silu(v^T W_down_s + b) ----
        if (tid >= 256 && tid < 256 + TILE * 3) {
            const int tt = tid - 256;
            const int r = tt / 3, f = tt % 3;
            const float* vr = gv + (size_t)(row0 + r) * 192;
            float a0 = 0.f, a1 = 0.f, a2 = 0.f;
            #pragma unroll 8
            for (int k = 0; k < 64; k++) {
                float vk = vr[k * 3 + f];
                a0 += vk * sWds[k * 4 + 0];
                a1 += vk * sWds[k * 4 + 1];
                a2 += vk * sWds[k * 4 + 2];
            }
            a0 += sbds[0]; a1 += sbds[1]; a2 += sbds[2];
            sVs[r * 12 + f * 3 + 0] = a0 * sigm(a0);
            sVs[r * 12 + f * 3 + 1] = a1 * sigm(a1);
            sVs[r * 12 + f * 3 + 2] = a2 * sigm(a2);
        }
        __syncthreads();

        // ---- A4: scalarized = frames @ vs -> slots 128..136 ----
        if (tid < TILE * 3) {
            const int r = tid / 3, f = tid % 3;
            const float* fr = gframes + (size_t)(row0 + r) * 9 + f * 3;
            float f0 = fr[0], f1 = fr[1], f2 = fr[2];
            #pragma unroll
            for (int d = 0; d < 3; d++) {
                float val = f0 * sVs[r * 12 + 0 + d] + f1 * sVs[r * 12 + 3 + d] +
                            f2 * sVs[r * 12 + 6 + d];
                __nv_bfloat16 h = __float2bfloat16(val);
                const int slot = 128 + f * 3 + d;
                *(__nv_bfloat16*)(smem + OFF_AH + (r * KSTR + slot) * 2) = h;
                *(__nv_bfloat16*)(smem + OFF_AL + (r * KSTR + slot) * 2) =
                    __float2bfloat16(val - __bfloat162float(h));
            }
        }
        __syncthreads();

        // ---- GEMM: [64 x 192 x 160] bf16 mma, 3 precision passes ----
        // warp tile: rows mw..mw+15, cols nw..nw+47 (6 n-frags)
        const int mw = (wid & 3) * 16;
        const int nw = (wid >> 2) * 48;
        float C[6][4];
        #pragma unroll
        for (int j = 0; j < 6; j++)
            #pragma unroll
            for (int q = 0; q < 4; q++) C[j][q] = 0.0f;

        #pragma unroll
        for (int p = 0; p < 3; p++) {
            const char* Ab = smem + (p == 1 ? OFF_AL : OFF_AH);
            const char* Wb = smem + (p == 2 ? OFF_WL : OFF_WH);
            const char* Ar = Ab + (mw + g) * (KSTR * 2) + t * 4;
            const char* Wr0 = Wb + (nw + g) * (KSTR * 2) + t * 4;
            #pragma unroll 2
            for (int ks = 0; ks < 10; ks++) {
                const int kb = ks * 32;
                uint32_t a0 = *(const uint32_t*)(Ar + kb);
                uint32_t a1 = *(const uint32_t*)(Ar + kb + 8 * KSTR * 2);
                uint32_t a2 = *(const uint32_t*)(Ar + kb + 16);
                uint32_t a3 = *(const uint32_t*)(Ar + kb + 8 * KSTR * 2 + 16);
                #pragma unroll
                for (int j = 0; j < 6; j++) {
                    const char* Wr = Wr0 + j * 8 * (KSTR * 2) + kb;
                    uint32_t b0 = *(const uint32_t*)(Wr);
                    uint32_t b1 = *(const uint32_t*)(Wr + 16);
                    mma16816(C[j], a0, a1, a2, a3, b0, b1);
                }
            }
        }

        // ---- epilogue: bias + silu -> gmem (n<128); sigmoid -> gate smem (n>=128) ----
        {
            const int r1 = mw + g, r2 = mw + g + 8;
            #pragma unroll
            for (int j = 0; j < 6; j++) {
                const int n0 = nw + 8 * j + 2 * t;
                if (n0 < 128) {
                    float b0 = sbso[n0], b1 = sbso[n0 + 1];
                    float v0 = C[j][0] + b0, v1 = C[j][1] + b1;
                    float v2 = C[j][2] + b0, v3 = C[j][3] + b1;
                    float2 o1 = {v0 * sigm(v0), v1 * sigm(v1)};
                    float2 o2 = {v2 * sigm(v2), v3 * sigm(v3)};
                    *(float2*)&outS[(size_t)(row0 + r1) * 128 + n0] = o1;
                    *(float2*)&outS[(size_t)(row0 + r2) * 128 + n0] = o2;
                } else {
                    const int c = n0 - 128;
                    float b0 = sbf[c], b1 = sbf[c + 1];
                    gate[r1 * GSTR + c]     = sigm(C[j][0] + b0);
                    gate[r1 * GSTR + c + 1] = sigm(C[j][1] + b1);
                    gate[r2 * GSTR + c]     = sigm(C[j][2] + b0);
                    gate[r2 * GSTR + c + 1] = sigm(C[j][3] + b1);
                }
            }
        }
        __syncthreads();

        // ---- Phase D: v_up = z @ W_up ; v_out = v_up^T * gate ----
        {
            const int r = tid >> 3, o0 = (tid & 7) * 8;
            float z[3][16];
            #pragma unroll
            for (int f = 0; f < 3; f++)
                #pragma unroll
                for (int q = 0; q < 4; q++) {
                    float4 zz = *(const float4*)&sZ[r * 52 + f * 16 + q * 4];
                    z[f][q * 4 + 0] = zz.x; z[f][q * 4 + 1] = zz.y;
                    z[f][q * 4 + 2] = zz.z; z[f][q * 4 + 3] = zz.w;
                }
            float gg[8];
            #pragma unroll
            for (int q = 0; q < 2; q++) {
                float4 g4 = *(const float4*)&gate[r * GSTR + o0 + q * 4];
                gg[q * 4 + 0] = g4.x; gg[q * 4 + 1] = g4.y;
                gg[q * 4 + 2] = g4.z; gg[q * 4 + 3] = g4.w;
            }
            float* ov = outV + (size_t)(row0 + r) * 192 + o0 * 3;
            #pragma unroll
            for (int oq = 0; oq < 2; oq++) {
                float acc[3][4];
                #pragma unroll
                for (int f = 0; f < 3; f++)
                    #pragma unroll
                    for (int m = 0; m < 4; m++) acc[f][m] = 0.0f;
                #pragma unroll
                for (int h = 0; h < 16; h++) {
                    float4 w = *(const float4*)&sWu[h * 64 + o0 + oq * 4];
                    acc[0][0] += z[0][h] * w.x; acc[0][1] += z[0][h] * w.y;
                    acc[0][2] += z[0][h] * w.z; acc[0][3] += z[0][h] * w.w;
                    acc[1][0] += z[1][h] * w.x; acc[1][1] += z[1][h] * w.y;
                    acc[1][2] += z[1][h] * w.z; acc[1][3] += z[1][h] * w.w;
                    acc[2][0] += z[2][h] * w.x; acc[2][1] += z[2][h] * w.y;
                    acc[2][2] += z[2][h] * w.z; acc[2][3] += z[2][h] * w.w;
                }
                float vals[12];
                #pragma unroll
                for (int m = 0; m < 4; m++) {
                    float gm = gg[oq * 4 + m];
                    vals[m * 3 + 0] = acc[0][m] * gm;
                    vals[m * 3 + 1] = acc[1][m] * gm;
                    vals[m * 3 + 2] = acc[2][m] * gm;
                }
                float4 t0 = {vals[0], vals[1], vals[2],  vals[3]};
                float4 t1 = {vals[4], vals[5], vals[6],  vals[7]};
                float4 t2 = {vals[8], vals[9], vals[10], vals[11]};
                *(float4*)(ov + oq * 12 + 0) = t0;
                *(float4*)(ov + oq * 12 + 4) = t1;
                *(float4*)(ov + oq * 12 + 8) = t2;
            }
        }
        __syncthreads();   // protect sZ/gate/A before next tile
    }
}

extern "C" void kernel_launch(void* const* d_in, const int* in_sizes, int n_in,
                              void* d_out, int out_size) {
    const float* s      = (const float*)d_in[0];
    const float* v      = (const float*)d_in[1];
    const float* frames = (const float*)d_in[2];
    const float* Wd     = (const float*)d_in[3];
    const float* Wds    = (const float*)d_in[4];
    const float* bds    = (const float*)d_in[5];
    const float* Wu     = (const float*)d_in[6];
    const float* Wso    = (const float*)d_in[7];
    const float* bso    = (const float*)d_in[8];
    const float* Wg     = (const float*)d_in[9];
    const float* bg     = (const float*)d_in[10];
    float* out          = (float*)d_out;

    int dev = 0;
    cudaGetDevice(&dev);
    int smCount = 148;
    cudaDeviceGetAttribute(&smCount, cudaDevAttrMultiProcessorCount, dev);

    cudaFuncSetAttribute(fused_tpp_mma,
                         cudaFuncAttributeMaxDynamicSharedMemorySize, SMEM_BYTES);
    fused_tpp_mma<<<smCount, THREADS, SMEM_BYTES>>>(s, v, frames, Wd, Wds, bds, Wu,
                                                    Wso, bso, Wg, bg, out);
}

// round 10
// speedup vs baseline: 1.3817x; 1.0416x over previous
#include <cuda_runtime.h>
#include <cuda_bf16.h>
#include <stdint.h>
#include <math.h>

constexpr int N_ROWS  = 400000;
constexpr int TILE    = 64;
constexpr int THREADS = 768;
constexpr int NT      = N_ROWS / TILE;   // 6250

constexpr int KSTR = 168;                // bf16 k-stride (conflict-free frags)
constexpr int GSTR = 68;                 // gate f32 stride

// smem byte offsets
constexpr int OFF_WH  = 0;                         // 64512: W_hi bf16 [192][168]
constexpr int OFF_WL  = OFF_WH + 192 * KSTR * 2;   // 64512
constexpr int OFF_AH  = OFF_WL + 192 * KSTR * 2;   // 21504: A_hi bf16 [64][168]
constexpr int OFF_AL  = OFF_AH + 64 * KSTR * 2;    // 21504
constexpr int OFF_Z   = OFF_AL + 64 * KSTR * 2;    // 13312: z f32 [64][52]
constexpr int OFF_G   = OFF_Z + 64 * 52 * 4;       // 17408: gate f32 [64][68]
constexpr int OFF_VS  = OFF_G + 64 * GSTR * 4;     // 3072:  vs f32 [64][12]
constexpr int OFF_WD  = OFF_VS + 64 * 12 * 4;      // 4096
constexpr int OFF_WU  = OFF_WD + 4096;             // 4096
constexpr int OFF_WDS = OFF_WU + 4096;             // 1024
constexpr int OFF_BSO = OFF_WDS + 1024;            // 512
constexpr int OFF_BF  = OFF_BSO + 512;             // 256
constexpr int OFF_BDS = OFF_BF + 256;              // 16
constexpr int SMEM_BYTES = OFF_BDS + 64;           // ~215 KB

__device__ __forceinline__ float sigm(float x) { return 1.0f / (1.0f + __expf(-x)); }

__device__ __forceinline__ uint32_t bf2(float a, float b) {
    __nv_bfloat162 h; h.x = __float2bfloat16(a); h.y = __float2bfloat16(b);
    return *reinterpret_cast<uint32_t*>(&h);
}
__device__ __forceinline__ uint32_t bf2hi(float a, float b, float& la, float& lb) {
    __nv_bfloat16 ha = __float2bfloat16(a), hb = __float2bfloat16(b);
    la = a - __bfloat162float(ha);
    lb = b - __bfloat162float(hb);
    __nv_bfloat162 h; h.x = ha; h.y = hb;
    return *reinterpret_cast<uint32_t*>(&h);
}
__device__ __forceinline__ void mma16816(float* c, uint32_t a0, uint32_t a1, uint32_t a2,
                                         uint32_t a3, uint32_t b0, uint32_t b1) {
    asm volatile(
        "mma.sync.aligned.m16n8k16.row.col.f32.bf16.bf16.f32 "
        "{%0,%1,%2,%3}, {%4,%5,%6,%7}, {%8,%9}, {%0,%1,%2,%3};"
        : "+f"(c[0]), "+f"(c[1]), "+f"(c[2]), "+f"(c[3])
        : "r"(a0), "r"(a1), "r"(a2), "r"(a3), "r"(b0), "r"(b1));
}

__global__ void __launch_bounds__(THREADS, 1)
fused_tpp_mma(const float* __restrict__ gs, const float* __restrict__ gv,
              const float* __restrict__ gframes,
              const float* __restrict__ gWd, const float* __restrict__ gWds,
              const float* __restrict__ gbds, const float* __restrict__ gWu,
              const float* __restrict__ gWso, const float* __restrict__ gbso,
              const float* __restrict__ gWg, const float* __restrict__ gbg,
              float* __restrict__ out)
{
    extern __shared__ char smem[];
    float* sZ   = (float*)(smem + OFF_Z);
    float* gate = (float*)(smem + OFF_G);
    float* sVs  = (float*)(smem + OFF_VS);
    float* sWd  = (float*)(smem + OFF_WD);
    float* sWu  = (float*)(smem + OFF_WU);
    float* sWds = (float*)(smem + OFF_WDS);
    float* sbso = (float*)(smem + OFF_BSO);
    float* sbf  = (float*)(smem + OFF_BF);
    float* sbds = (float*)(smem + OFF_BDS);

    const int tid  = threadIdx.x;
    const int wid  = tid >> 5;
    const int lane = tid & 31;
    const int g    = lane >> 2;           // fragment group 0..7
    const int t    = lane & 3;            // thread-in-group

    // ---- one-time staging ----
    for (int i = tid; i < 64 * 16; i += THREADS) sWd[i] = gWd[i];
    for (int i = tid; i < 16 * 64; i += THREADS) sWu[i] = gWu[i];
    if (tid < 64) {
        sWds[tid * 4 + 0] = gWds[tid * 3 + 0];
        sWds[tid * 4 + 1] = gWds[tid * 3 + 1];
        sWds[tid * 4 + 2] = gWds[tid * 3 + 2];
        sWds[tid * 4 + 3] = 0.0f;
    }
    if (tid < 128) sbso[tid] = gbso[tid];
    if (tid < 4)   sbds[tid] = (tid < 3) ? gbds[tid] : 0.0f;
    if (tid < 64) {
        float acc = gbg[tid];
        for (int j = 0; j < 128; j++) acc += gbso[j] * gWg[j * 64 + tid];
        sbf[tid] = acc;
    }
    // fused gate weight Wf[k][n] = sum_j Wso[k][j]*Wg[j][n]  (scratch in A region)
    float* wf = (float*)(smem + OFF_AH);   // [153][64]
    for (int idx = tid; idx < 153 * 64; idx += THREADS) {
        int k = idx >> 6, n = idx & 63;
        float acc = 0.f;
        #pragma unroll 4
        for (int j = 0; j < 128; j++) acc += gWso[k * 128 + j] * gWg[j * 64 + n];
        wf[idx] = acc;
    }
    __syncthreads();
    // W_hi / W_lo: [192 n][KSTR k] bf16, rows n<128 = Wso col n, n>=128 = Wf col n-128
    for (int i = tid; i < 192 * KSTR; i += THREADS) {
        int n = i / KSTR, k = i % KSTR;
        float w = 0.f;
        if (k < 153) w = (n < 128) ? gWso[k * 128 + n] : wf[k * 64 + (n - 128)];
        __nv_bfloat16 h = __float2bfloat16(w);
        *(__nv_bfloat16*)(smem + OFF_WH + i * 2) = h;
        *(__nv_bfloat16*)(smem + OFF_WL + i * 2) = __float2bfloat16(w - __bfloat162float(h));
    }
    __syncthreads();
    // zero A_hi + A_lo (pads 153..167 stay zero forever)
    for (int i = tid; i < (2 * 64 * KSTR * 2) / 4; i += THREADS)
        ((uint32_t*)(smem + OFF_AH))[i] = 0;
    __syncthreads();

    float* outS = out;
    float* outV = out + (size_t)N_ROWS * 128;

    for (int tile = blockIdx.x; tile < NT; tile += gridDim.x) {
        const int row0 = tile * TILE;

        // ---- A1: s -> A_hi/A_lo slots 0..127 (512 units: row x 16-col group) ----
        if (tid < 512) {
            const int rr = tid >> 3, c0 = (tid & 7) * 16;
            const float4* sr = (const float4*)(gs + (size_t)(row0 + rr) * 128 + c0);
            char* ah = smem + OFF_AH + rr * (KSTR * 2) + c0 * 2;
            char* al = smem + OFF_AL + rr * (KSTR * 2) + c0 * 2;
            #pragma unroll
            for (int q = 0; q < 4; q++) {
                float4 x = sr[q];
                float la, lb, lc, ld;
                uint32_t h0 = bf2hi(x.x, x.y, la, lb);
                uint32_t h1 = bf2hi(x.z, x.w, lc, ld);
                *(uint32_t*)(ah + q * 8)     = h0;
                *(uint32_t*)(ah + q * 8 + 4) = h1;
                *(uint32_t*)(al + q * 8)     = bf2(la, lb);
                *(uint32_t*)(al + q * 8 + 4) = bf2(lc, ld);
            }
        }

        // ---- A2: z = v^T W_down ; norms -> slots 137..152 ----
        if (tid < 256) {
            const int r = tid >> 2, j = tid & 3, h0 = j * 4;
            const float4* vr = (const float4*)(gv + (size_t)(row0 + r) * 192);
            float az[12];
            #pragma unroll
            for (int i = 0; i < 12; i++) az[i] = 0.0f;
            #pragma unroll 4
            for (int kc = 0; kc < 16; kc++) {
                float4 p0 = vr[kc * 3 + 0];
                float4 p1 = vr[kc * 3 + 1];
                float4 p2 = vr[kc * 3 + 2];
                float vk[4][3] = {{p0.x, p0.y, p0.z}, {p0.w, p1.x, p1.y},
                                  {p1.z, p1.w, p2.x}, {p2.y, p2.z, p2.w}};
                #pragma unroll
                for (int kk = 0; kk < 4; kk++) {
                    const int k = kc * 4 + kk;
                    float4 w = *(const float4*)&sWd[k * 16 + h0];
                    az[0] += vk[kk][0] * w.x; az[1]  += vk[kk][0] * w.y;
                    az[2] += vk[kk][0] * w.z; az[3]  += vk[kk][0] * w.w;
                    az[4] += vk[kk][1] * w.x; az[5]  += vk[kk][1] * w.y;
                    az[6] += vk[kk][1] * w.z; az[7]  += vk[kk][1] * w.w;
                    az[8] += vk[kk][2] * w.x; az[9]  += vk[kk][2] * w.y;
                    az[10]+= vk[kk][2] * w.z; az[11] += vk[kk][2] * w.w;
                }
            }
            #pragma unroll
            for (int i = 0; i < 4; i++) {
                float z0 = az[i], z1 = az[4 + i], z2 = az[8 + i];
                sZ[r * 52 + 0  + h0 + i] = z0;
                sZ[r * 52 + 16 + h0 + i] = z1;
                sZ[r * 52 + 32 + h0 + i] = z2;
                float nr = sqrtf(z0 * z0 + z1 * z1 + z2 * z2);
                __nv_bfloat16 h = __float2bfloat16(nr);
                const int slot = 137 + h0 + i;
                *(__nv_bfloat16*)(smem + OFF_AH + (r * KSTR + slot) * 2) = h;
                *(__nv_bfloat16*)(smem + OFF_AL + (r * KSTR + slot) * 2) =
                    __float2bfloat16(nr - __bfloat162float(h));
            }
        }

        // ---- A3: vs = silu(v^T W_down_s + b) ----
        if (tid >= 256 && tid < 256 + TILE * 3) {
            const int tt = tid - 256;
            const int r = tt / 3, f = tt % 3;
            const float* vr = gv + (size_t)(row0 + r) * 192;
            float a0 = 0.f, a1 = 0.f, a2 = 0.f;
            #pragma unroll 8
            for (int k = 0; k < 64; k++) {
                float vk = vr[k * 3 + f];
                a0 += vk * sWds[k * 4 + 0];
                a1 += vk * sWds[k * 4 + 1];
                a2 += vk * sWds[k * 4 + 2];
            }
            a0 += sbds[0]; a1 += sbds[1]; a2 += sbds[2];
            sVs[r * 12 + f * 3 + 0] = a0 * sigm(a0);
            sVs[r * 12 + f * 3 + 1] = a1 * sigm(a1);
            sVs[r * 12 + f * 3 + 2] = a2 * sigm(a2);
        }
        __syncthreads();

        // ---- A4: scalarized = frames @ vs -> slots 128..136 ----
        if (tid < TILE * 3) {
            const int r = tid / 3, f = tid % 3;
            const float* fr = gframes + (size_t)(row0 + r) * 9 + f * 3;
            float f0 = fr[0], f1 = fr[1], f2 = fr[2];
            #pragma unroll
            for (int d = 0; d < 3; d++) {
                float val = f0 * sVs[r * 12 + 0 + d] + f1 * sVs[r * 12 + 3 + d] +
                            f2 * sVs[r * 12 + 6 + d];
                __nv_bfloat16 h = __float2bfloat16(val);
                const int slot = 128 + f * 3 + d;
                *(__nv_bfloat16*)(smem + OFF_AH + (r * KSTR + slot) * 2) = h;
                *(__nv_bfloat16*)(smem + OFF_AL + (r * KSTR + slot) * 2) =
                    __float2bfloat16(val - __bfloat162float(h));
            }
        }
        __syncthreads();

        // ---- GEMM: [64 x 192 x 160] bf16 mma, 3 precision passes ----
        // 24 warps: warp tile rows mw..mw+15, cols nw..nw+31 (4 n-frags)
        const int mw = (wid & 3) * 16;
        const int nw = (wid >> 2) * 32;
        float C[4][4];
        #pragma unroll
        for (int j = 0; j < 4; j++)
            #pragma unroll
            for (int q = 0; q < 4; q++) C[j][q] = 0.0f;

        #pragma unroll
        for (int p = 0; p < 3; p++) {
            const char* Ab = smem + (p == 1 ? OFF_AL : OFF_AH);
            const char* Wb = smem + (p == 2 ? OFF_WL : OFF_WH);
            const char* Ar = Ab + (mw + g) * (KSTR * 2) + t * 4;
            const char* Wr0 = Wb + (nw + g) * (KSTR * 2) + t * 4;
            #pragma unroll 2
            for (int ks = 0; ks < 10; ks++) {
                const int kb = ks * 32;
                uint32_t a0 = *(const uint32_t*)(Ar + kb);
                uint32_t a1 = *(const uint32_t*)(Ar + kb + 8 * KSTR * 2);
                uint32_t a2 = *(const uint32_t*)(Ar + kb + 16);
                uint32_t a3 = *(const uint32_t*)(Ar + kb + 8 * KSTR * 2 + 16);
                #pragma unroll
                for (int j = 0; j < 4; j++) {
                    const char* Wr = Wr0 + j * 8 * (KSTR * 2) + kb;
                    uint32_t b0 = *(const uint32_t*)(Wr);
                    uint32_t b1 = *(const uint32_t*)(Wr + 16);
                    mma16816(C[j], a0, a1, a2, a3, b0, b1);
                }
            }
        }

        // ---- epilogue: bias + silu -> gmem (n<128); sigmoid -> gate smem (n>=128) ----
        {
            const int r1 = mw + g, r2 = mw + g + 8;
            #pragma unroll
            for (int j = 0; j < 4; j++) {
                const int n0 = nw + 8 * j + 2 * t;
                if (n0 < 128) {
                    float b0 = sbso[n0], b1 = sbso[n0 + 1];
                    float v0 = C[j][0] + b0, v1 = C[j][1] + b1;
                    float v2 = C[j][2] + b0, v3 = C[j][3] + b1;
                    float2 o1 = {v0 * sigm(v0), v1 * sigm(v1)};
                    float2 o2 = {v2 * sigm(v2), v3 * sigm(v3)};
                    *(float2*)&outS[(size_t)(row0 + r1) * 128 + n0] = o1;
                    *(float2*)&outS[(size_t)(row0 + r2) * 128 + n0] = o2;
                } else {
                    const int c = n0 - 128;
                    float b0 = sbf[c], b1 = sbf[c + 1];
                    gate[r1 * GSTR + c]     = sigm(C[j][0] + b0);
                    gate[r1 * GSTR + c + 1] = sigm(C[j][1] + b1);
                    gate[r2 * GSTR + c]     = sigm(C[j][2] + b0);
                    gate[r2 * GSTR + c + 1] = sigm(C[j][3] + b1);
                }
            }
        }
        __syncthreads();

        // ---- Phase D: v_up = z @ W_up ; v_out = v_up^T * gate ----
        if (tid < 512) {
            const int r = tid >> 3, o0 = (tid & 7) * 8;
            float z[3][16];
            #pragma unroll
            for (int f = 0; f < 3; f++)
                #pragma unroll
                for (int q = 0; q < 4; q++) {
                    float4 zz = *(const float4*)&sZ[r * 52 + f * 16 + q * 4];
                    z[f][q * 4 + 0] = zz.x; z[f][q * 4 + 1] = zz.y;
                    z[f][q * 4 + 2] = zz.z; z[f][q * 4 + 3] = zz.w;
                }
            float* ov = outV + (size_t)(row0 + r) * 192 + o0 * 3;
            #pragma unroll
            for (int oq = 0; oq < 2; oq++) {
                float gg[4];
                float4 g4 = *(const float4*)&gate[r * GSTR + o0 + oq * 4];
                gg[0] = g4.x; gg[1] = g4.y; gg[2] = g4.z; gg[3] = g4.w;
                float acc[3][4];
                #pragma unroll
                for (int f = 0; f < 3; f++)
                    #pragma unroll
                    for (int m = 0; m < 4; m++) acc[f][m] = 0.0f;
                #pragma unroll
                for (int h = 0; h < 16; h++) {
                    float4 w = *(const float4*)&sWu[h * 64 + o0 + oq * 4];
                    acc[0][0] += z[0][h] * w.x; acc[0][1] += z[0][h] * w.y;
                    acc[0][2] += z[0][h] * w.z; acc[0][3] += z[0][h] * w.w;
                    acc[1][0] += z[1][h] * w.x; acc[1][1] += z[1][h] * w.y;
                    acc[1][2] += z[1][h] * w.z; acc[1][3] += z[1][h] * w.w;
                    acc[2][0] += z[2][h] * w.x; acc[2][1] += z[2][h] * w.y;
                    acc[2][2] += z[2][h] * w.z; acc[2][3] += z[2][h] * w.w;
                }
                float vals[12];
                #pragma unroll
                for (int m = 0; m < 4; m++) {
                    float gm = gg[m];
                    vals[m * 3 + 0] = acc[0][m] * gm;
                    vals[m * 3 + 1] = acc[1][m] * gm;
                    vals[m * 3 + 2] = acc[2][m] * gm;
                }
                float4 t0 = {vals[0], vals[1], vals[2],  vals[3]};
                float4 t1 = {vals[4], vals[5], vals[6],  vals[7]};
                float4 t2 = {vals[8], vals[9], vals[10], vals[11]};
                *(float4*)(ov + oq * 12 + 0) = t0;
                *(float4*)(ov + oq * 12 + 4) = t1;
                *(float4*)(ov + oq * 12 + 8) = t2;
            }
        }
        __syncthreads();   // protect sZ/gate/A before next tile
    }
}

extern "C" void kernel_launch(void* const* d_in, const int* in_sizes, int n_in,
                              void* d_out, int out_size) {
    const float* s      = (const float*)d_in[0];
    const float* v      = (const float*)d_in[1];
    const float* frames = (const float*)d_in[2];
    const float* Wd     = (const float*)d_in[3];
    const float* Wds    = (const float*)d_in[4];
    const float* bds    = (const float*)d_in[5];
    const float* Wu     = (const float*)d_in[6];
    const float* Wso    = (const float*)d_in[7];
    const float* bso    = (const float*)d_in[8];
    const float* Wg     = (const float*)d_in[9];
    const float* bg     = (const float*)d_in[10];
    float* out          = (float*)d_out;

    int dev = 0;
    cudaGetDevice(&dev);
    int smCount = 148;
    cudaDeviceGetAttribute(&smCount, cudaDevAttrMultiProcessorCount, dev);

    cudaFuncSetAttribute(fused_tpp_mma,
                         cudaFuncAttributeMaxDynamicSharedMemorySize, SMEM_BYTES);
    fused_tpp_mma<<<smCount, THREADS, SMEM_BYTES>>>(s, v, frames, Wd, Wds, bds, Wu,
                                                    Wso, bso, Wg, bg, out);
}